// round 5
// baseline (speedup 1.0000x reference)
#include <cuda_runtime.h>

#define NN 50000
#define EE 800000
#define FIN 128
#define HH 64
#define HX 128   // 2H

#define MSG_EPS 1e-7f
#define SCAN_NBLK ((NN + 255) / 256)   // 196
#define EDGE_BLOCKS ((EE + 255) / 256) // 3125
#define ENC_BLOCKS ((NN + 255) / 256)  // 196

// ---------------- device scratch (no allocation allowed) ----------------
__device__ int   g_srcSorted[EE];
__device__ int   g_cnt[NN];            // must be 0 at run start (zeroed at run end)
__device__ int   g_off[NN + 1];
__device__ int   g_cursor[NN];
__device__ volatile unsigned long long g_state[SCAN_NBLK];  // lookback state, 0 at start
__device__ float g_xenc[NN * HH];
__device__ float g_tmp[NN * HH];   // agg + residual (gen_conv "out")
__device__ float g_x1[NN * HH];    // conv1 output

// -------- inline dtype detect helper (first 512 words of edge_index) ------
// If data is int64, every odd 32-bit word is a high-word of a value < 2^31
// -> zero. If int32, those words are random node ids.
__device__ __forceinline__ int detect_is64(const int* __restrict__ ei32,
                                           int t, int* s_flag) {
    int v = ei32[2 * (t & 255) + 1];
    int any = __syncthreads_or(v != 0);
    if (t == 0) *s_flag = !any;
    __syncthreads();
    return *s_flag;
}

__device__ __forceinline__ void decode_edge(const int* __restrict__ ei32,
                                            int is64, int e, int* s, int* d) {
    if (is64) {
        const long long* p = (const long long*)ei32;
        *s = (int)p[e];
        *d = (int)p[EE + e];
    } else {
        *s = ei32[e];
        *d = ei32[EE + e];
    }
}

// ---------------- count degrees ----------------
__global__ void count_kernel(const int* __restrict__ ei32) {
    __shared__ int s_is64;
    int t = threadIdx.x;
    int is64 = detect_is64(ei32, t, &s_is64);
    int e = blockIdx.x * blockDim.x + t;
    if (e >= EE) return;
    int s, d;
    decode_edge(ei32, is64, e, &s, &d);
    atomicAdd(&g_cnt[d], 1);
}

// ---- block exclusive scan helper ----
__device__ __forceinline__ int block_excl_scan_256(int v, int* wsum, int t) {
    int lane = t & 31;
    int w = t >> 5;
    int incl = v;
#pragma unroll
    for (int o = 1; o < 32; o <<= 1) {
        int n = __shfl_up_sync(0xffffffffu, incl, o);
        if (lane >= o) incl += n;
    }
    if (lane == 31) wsum[w] = incl;
    __syncthreads();
    if (t == 0) {
        int run = 0;
#pragma unroll
        for (int i = 0; i < 8; i++) { int c = wsum[i]; wsum[i] = run; run += c; }
        wsum[8] = run;  // block total
    }
    __syncthreads();
    return incl - v + wsum[w];
}

// ---- single-pass decoupled-lookback scan: g_cnt -> g_off, g_cursor ----
__global__ void scan_lb_kernel() {
    __shared__ int wsum[9];
    __shared__ int s_excl;
    int b = blockIdx.x, t = threadIdx.x;
    int idx = b * 256 + t;
    int v = (idx < NN) ? g_cnt[idx] : 0;
    int excl = block_excl_scan_256(v, wsum, t);
    int total = wsum[8];

    if (t == 0) {
        unsigned long long st = (b == 0)
            ? ((2ULL << 32) | (unsigned)total)
            : ((1ULL << 32) | (unsigned)total);
        atomicExch((unsigned long long*)&g_state[b], st);
        if (b == 0) s_excl = 0;
    }
    if (b > 0 && t < 32) {
        int lane = t;
        int look = b - 1;
        int run = 0;
        while (true) {
            int ip = look - lane;
            unsigned long long s;
            if (ip >= 0) {
                do { s = g_state[ip]; } while ((s >> 32) == 0);
            } else {
                s = (2ULL << 32);
            }
            int isPref = ((s >> 32) == 2u);
            unsigned mask = __ballot_sync(0xffffffffu, isPref);
            int val = (int)(s & 0xffffffffu);
            if (mask) {
                int p = __ffs(mask) - 1;
                int contrib = (lane <= p) ? val : 0;
#pragma unroll
                for (int o = 16; o; o >>= 1) contrib += __shfl_xor_sync(0xffffffffu, contrib, o);
                run += contrib;
                break;
            } else {
                int contrib = val;
#pragma unroll
                for (int o = 16; o; o >>= 1) contrib += __shfl_xor_sync(0xffffffffu, contrib, o);
                run += contrib;
                look -= 32;
            }
        }
        if (lane == 0) {
            s_excl = run;
            atomicExch((unsigned long long*)&g_state[b],
                       (2ULL << 32) | (unsigned)(run + total));
        }
    }
    __syncthreads();
    int base = s_excl;
    if (idx < NN) { int off = excl + base; g_off[idx] = off; g_cursor[idx] = off; }
    if (b == SCAN_NBLK - 1 && t == 0) g_off[NN] = EE;
}

// ---------------- scatter edges into CSR order ----------------
__global__ void scatter_kernel(const int* __restrict__ ei32) {
    __shared__ int s_is64;
    int t = threadIdx.x;
    int is64 = detect_is64(ei32, t, &s_is64);
    int e = blockIdx.x * blockDim.x + t;
    if (e >= EE) return;
    int s, d;
    decode_edge(ei32, is64, e, &s, &d);
    int pos = atomicAdd(&g_cursor[d], 1);
    g_srcSorted[pos] = s;
}

// ---------------- encoder GEMM: x[N,128] @ W[128,64] + b ----------------
__global__ void __launch_bounds__(256) encoder_kernel(
    const float* __restrict__ x, const float* __restrict__ W,
    const float* __restrict__ b) {
    __shared__ float Ws[FIN * HH];  // 32 KB
    for (int i = threadIdx.x; i < FIN * HH; i += blockDim.x) Ws[i] = W[i];
    __syncthreads();
    int row = blockIdx.x * blockDim.x + threadIdx.x;
    if (row >= NN) return;

    float4 acc[16];
#pragma unroll
    for (int i = 0; i < 16; i++) acc[i] = make_float4(0.f, 0.f, 0.f, 0.f);

    const float4* xr = (const float4*)(x + (size_t)row * FIN);
    const float4* W4 = (const float4*)Ws;
#pragma unroll 4
    for (int k4 = 0; k4 < FIN / 4; k4++) {
        float4 a = xr[k4];
        float av[4] = {a.x, a.y, a.z, a.w};
#pragma unroll
        for (int kk = 0; kk < 4; kk++) {
            int k = k4 * 4 + kk;
            float aval = av[kk];
#pragma unroll
            for (int c = 0; c < 16; c++) {
                float4 w = W4[k * 16 + c];
                acc[c].x += aval * w.x;
                acc[c].y += aval * w.y;
                acc[c].z += aval * w.z;
                acc[c].w += aval * w.w;
            }
        }
    }
    const float4* b4 = (const float4*)b;
    float4* outp = (float4*)(g_xenc + (size_t)row * HH);
#pragma unroll
    for (int c = 0; c < 16; c++) {
        float4 bb = b4[c];
        outp[c] = make_float4(acc[c].x + bb.x, acc[c].y + bb.y,
                              acc[c].z + bb.z, acc[c].w + bb.w);
    }
}

// ---------------- softmax aggregation: warp per dst node ----------------
__global__ void agg_kernel(int sel, const float* __restrict__ tptr) {
    const float* __restrict__ xin = sel ? g_x1 : g_xenc;
    int gw = (blockIdx.x * blockDim.x + threadIdx.x) >> 5;
    int lane = threadIdx.x & 31;
    if (gw >= NN) return;
    float t2 = (*tptr) * 1.44269504f;   // fold log2e into the logit scale
    int e0 = g_off[gw], e1 = g_off[gw + 1];

    float S0 = 0.f, S1 = 0.f, A0 = 0.f, A1 = 0.f;

    int e = e0;
    for (; e + 4 <= e1; e += 4) {
        int s0 = g_srcSorted[e];
        int s1 = g_srcSorted[e + 1];
        int s2 = g_srcSorted[e + 2];
        int s3 = g_srcSorted[e + 3];
        float a0 = xin[(size_t)s0 * HH + lane];
        float b0 = xin[(size_t)s0 * HH + 32 + lane];
        float a1 = xin[(size_t)s1 * HH + lane];
        float b1 = xin[(size_t)s1 * HH + 32 + lane];
        float a2 = xin[(size_t)s2 * HH + lane];
        float b2 = xin[(size_t)s2 * HH + 32 + lane];
        float a3 = xin[(size_t)s3 * HH + lane];
        float b3 = xin[(size_t)s3 * HH + 32 + lane];

        float m, ex;
        m = fmaxf(a0, 0.f) + MSG_EPS; ex = exp2f(m * t2); S0 += ex; A0 += m * ex;
        m = fmaxf(b0, 0.f) + MSG_EPS; ex = exp2f(m * t2); S1 += ex; A1 += m * ex;
        m = fmaxf(a1, 0.f) + MSG_EPS; ex = exp2f(m * t2); S0 += ex; A0 += m * ex;
        m = fmaxf(b1, 0.f) + MSG_EPS; ex = exp2f(m * t2); S1 += ex; A1 += m * ex;
        m = fmaxf(a2, 0.f) + MSG_EPS; ex = exp2f(m * t2); S0 += ex; A0 += m * ex;
        m = fmaxf(b2, 0.f) + MSG_EPS; ex = exp2f(m * t2); S1 += ex; A1 += m * ex;
        m = fmaxf(a3, 0.f) + MSG_EPS; ex = exp2f(m * t2); S0 += ex; A0 += m * ex;
        m = fmaxf(b3, 0.f) + MSG_EPS; ex = exp2f(m * t2); S1 += ex; A1 += m * ex;
    }
    for (; e < e1; e++) {
        int s = g_srcSorted[e];
        float a = xin[(size_t)s * HH + lane];
        float b = xin[(size_t)s * HH + 32 + lane];
        float m, ex;
        m = fmaxf(a, 0.f) + MSG_EPS; ex = exp2f(m * t2); S0 += ex; A0 += m * ex;
        m = fmaxf(b, 0.f) + MSG_EPS; ex = exp2f(m * t2); S1 += ex; A1 += m * ex;
    }
    float r0 = A0 / (S0 + 1e-16f);
    float r1 = A1 / (S1 + 1e-16f);
    g_tmp[(size_t)gw * HH + lane]      = r0 + xin[(size_t)gw * HH + lane];
    g_tmp[(size_t)gw * HH + 32 + lane] = r1 + xin[(size_t)gw * HH + 32 + lane];
}

// ---------------- fused MLP (conv1): relu(LN(row@W1+b1)) @ W2 + b2 -> g_x1 --
__global__ void __launch_bounds__(128) mlp1_kernel(
    const float* __restrict__ W1, const float* __restrict__ b1,
    const float* __restrict__ g1, const float* __restrict__ be1,
    const float* __restrict__ W2, const float* __restrict__ b2) {
    __shared__ float rowS[2 * HH];
    __shared__ float hS[2][HX];
    __shared__ float part[2][HX];
    __shared__ float sred[2][4], qred[2][4];

    int tid = threadIdx.x;
    int lane = tid & 31;
    int w = tid >> 5;
    int oc = tid & 63;
    int half = tid >> 6;

    float w1c[HH];
#pragma unroll
    for (int k = 0; k < HH; k++) w1c[k] = W1[k * HX + tid];
    float b1v = b1[tid], g1v = g1[tid], be1v = be1[tid];
    float w2c[64];
#pragma unroll
    for (int k = 0; k < 64; k++) w2c[k] = W2[(half * 64 + k) * HH + oc];
    float b2v = b2[oc];

    const int NPAIR = NN / 2;
    for (int p = blockIdx.x; p < NPAIR; p += gridDim.x) {
        int r0 = 2 * p;
        __syncthreads();
        rowS[tid] = g_tmp[(size_t)r0 * HH + tid];
        __syncthreads();

        float h0 = b1v, h1 = b1v;
        const float4* r4 = (const float4*)rowS;
#pragma unroll
        for (int k4 = 0; k4 < HH / 4; k4++) {
            float4 a = r4[k4];
            float4 b = r4[HH / 4 + k4];
            h0 += a.x * w1c[4 * k4] + a.y * w1c[4 * k4 + 1]
                + a.z * w1c[4 * k4 + 2] + a.w * w1c[4 * k4 + 3];
            h1 += b.x * w1c[4 * k4] + b.y * w1c[4 * k4 + 1]
                + b.z * w1c[4 * k4 + 2] + b.w * w1c[4 * k4 + 3];
        }
        float s0 = h0, q0 = h0 * h0, s1 = h1, q1 = h1 * h1;
#pragma unroll
        for (int o = 16; o; o >>= 1) {
            s0 += __shfl_xor_sync(0xffffffffu, s0, o);
            q0 += __shfl_xor_sync(0xffffffffu, q0, o);
            s1 += __shfl_xor_sync(0xffffffffu, s1, o);
            q1 += __shfl_xor_sync(0xffffffffu, q1, o);
        }
        if (lane == 0) { sred[0][w] = s0; qred[0][w] = q0; sred[1][w] = s1; qred[1][w] = q1; }
        __syncthreads();
        float S0 = sred[0][0] + sred[0][1] + sred[0][2] + sred[0][3];
        float Q0 = qred[0][0] + qred[0][1] + qred[0][2] + qred[0][3];
        float S1 = sred[1][0] + sred[1][1] + sred[1][2] + sred[1][3];
        float Q1 = qred[1][0] + qred[1][1] + qred[1][2] + qred[1][3];
        float mu0 = S0 * (1.f / HX);
        float mu1 = S1 * (1.f / HX);
        float rs0 = rsqrtf(Q0 * (1.f / HX) - mu0 * mu0 + 1e-5f);
        float rs1 = rsqrtf(Q1 * (1.f / HX) - mu1 * mu1 + 1e-5f);
        hS[0][tid] = fmaxf((h0 - mu0) * rs0 * g1v + be1v, 0.f);
        hS[1][tid] = fmaxf((h1 - mu1) * rs1 * g1v + be1v, 0.f);
        __syncthreads();

        float acc0 = 0.f, acc1 = 0.f;
        const float4* h40 = (const float4*)&hS[0][half * 64];
        const float4* h41 = (const float4*)&hS[1][half * 64];
#pragma unroll
        for (int k4 = 0; k4 < 16; k4++) {
            float4 a = h40[k4];
            float4 b = h41[k4];
            acc0 += a.x * w2c[4 * k4] + a.y * w2c[4 * k4 + 1]
                  + a.z * w2c[4 * k4 + 2] + a.w * w2c[4 * k4 + 3];
            acc1 += b.x * w2c[4 * k4] + b.y * w2c[4 * k4 + 1]
                  + b.z * w2c[4 * k4 + 2] + b.w * w2c[4 * k4 + 3];
        }
        part[0][tid] = acc0;
        part[1][tid] = acc1;
        __syncthreads();
        float v = part[half][oc] + part[half][oc + 64] + b2v;
        g_x1[(size_t)(r0 + half) * HH + oc] = v;
    }
}

// ------- conv2 MLP fused with the whole network epilogue -> d_out ---------
__global__ void __launch_bounds__(128) mlp2_final_kernel(
    const float* __restrict__ W1, const float* __restrict__ b1,
    const float* __restrict__ g1, const float* __restrict__ be1,
    const float* __restrict__ W2, const float* __restrict__ b2,
    const float* __restrict__ ln1g, const float* __restrict__ ln1b,
    const float* __restrict__ ng, const float* __restrict__ nb,
    const float* __restrict__ lw, const float* __restrict__ lb,
    float* __restrict__ out) {
    __shared__ float rowS[2 * HH];
    __shared__ float hS[2][HX];
    __shared__ float part[2][HX];
    __shared__ float sred[2][4], qred[2][4];
    __shared__ float f1s[2][2], f1q[2][2];
    __shared__ float f2s[2][2], f2q[2][2];
    __shared__ float fd[2][2];

    int tid = threadIdx.x;
    int lane = tid & 31;
    int w = tid >> 5;
    int oc = tid & 63;
    int half = tid >> 6;
    int wh = w & 1;

    float w1c[HH];
#pragma unroll
    for (int k = 0; k < HH; k++) w1c[k] = W1[k * HX + tid];
    float b1v = b1[tid], g1v = g1[tid], be1v = be1[tid];
    float w2c[64];
#pragma unroll
    for (int k = 0; k < 64; k++) w2c[k] = W2[(half * 64 + k) * HH + oc];
    float b2v = b2[oc];
    float l1g = ln1g[oc], l1b = ln1b[oc];
    float ngx = ng[oc], nbx = nb[oc];
    float ngh = ng[64 + oc], nbh = nb[64 + oc];
    float lwx = lw[oc], lwh = lw[64 + oc];
    float lbv = lb[0];

    const int NPAIR = NN / 2;
    for (int p = blockIdx.x; p < NPAIR; p += gridDim.x) {
        int r0 = 2 * p;
        __syncthreads();
        rowS[tid] = g_tmp[(size_t)r0 * HH + tid];
        __syncthreads();

        float h0 = b1v, h1 = b1v;
        const float4* r4 = (const float4*)rowS;
#pragma unroll
        for (int k4 = 0; k4 < HH / 4; k4++) {
            float4 a = r4[k4];
            float4 b = r4[HH / 4 + k4];
            h0 += a.x * w1c[4 * k4] + a.y * w1c[4 * k4 + 1]
                + a.z * w1c[4 * k4 + 2] + a.w * w1c[4 * k4 + 3];
            h1 += b.x * w1c[4 * k4] + b.y * w1c[4 * k4 + 1]
                + b.z * w1c[4 * k4 + 2] + b.w * w1c[4 * k4 + 3];
        }
        float s0 = h0, q0 = h0 * h0, s1 = h1, q1 = h1 * h1;
#pragma unroll
        for (int o = 16; o; o >>= 1) {
            s0 += __shfl_xor_sync(0xffffffffu, s0, o);
            q0 += __shfl_xor_sync(0xffffffffu, q0, o);
            s1 += __shfl_xor_sync(0xffffffffu, s1, o);
            q1 += __shfl_xor_sync(0xffffffffu, q1, o);
        }
        if (lane == 0) { sred[0][w] = s0; qred[0][w] = q0; sred[1][w] = s1; qred[1][w] = q1; }
        __syncthreads();
        float S0 = sred[0][0] + sred[0][1] + sred[0][2] + sred[0][3];
        float Q0 = qred[0][0] + qred[0][1] + qred[0][2] + qred[0][3];
        float S1 = sred[1][0] + sred[1][1] + sred[1][2] + sred[1][3];
        float Q1 = qred[1][0] + qred[1][1] + qred[1][2] + qred[1][3];
        float mu0 = S0 * (1.f / HX);
        float mu1 = S1 * (1.f / HX);
        float rs0 = rsqrtf(Q0 * (1.f / HX) - mu0 * mu0 + 1e-5f);
        float rs1 = rsqrtf(Q1 * (1.f / HX) - mu1 * mu1 + 1e-5f);
        hS[0][tid] = fmaxf((h0 - mu0) * rs0 * g1v + be1v, 0.f);
        hS[1][tid] = fmaxf((h1 - mu1) * rs1 * g1v + be1v, 0.f);
        __syncthreads();

        float acc0 = 0.f, acc1 = 0.f;
        const float4* h40 = (const float4*)&hS[0][half * 64];
        const float4* h41 = (const float4*)&hS[1][half * 64];
#pragma unroll
        for (int k4 = 0; k4 < 16; k4++) {
            float4 a = h40[k4];
            float4 b = h41[k4];
            acc0 += a.x * w2c[4 * k4] + a.y * w2c[4 * k4 + 1]
                  + a.z * w2c[4 * k4 + 2] + a.w * w2c[4 * k4 + 3];
            acc1 += b.x * w2c[4 * k4] + b.y * w2c[4 * k4 + 1]
                  + b.z * w2c[4 * k4 + 2] + b.w * w2c[4 * k4 + 3];
        }
        part[0][tid] = acc0;
        part[1][tid] = acc1;
        __syncthreads();

        // this thread owns h2 value of (row = r0+half, channel oc)
        float hv = part[half][oc] + part[half][oc + 64] + b2v;
        float xv = g_x1[(size_t)r0 * HH + tid];  // == g_x1[(r0+half)*64 + oc]

        // LN over 64 h-channels, relu
        float s = hv, q = hv * hv;
#pragma unroll
        for (int o = 16; o; o >>= 1) {
            s += __shfl_xor_sync(0xffffffffu, s, o);
            q += __shfl_xor_sync(0xffffffffu, q, o);
        }
        if (lane == 0) { f1s[half][wh] = s; f1q[half][wh] = q; }
        __syncthreads();
        float Sh = f1s[half][0] + f1s[half][1];
        float Qh = f1q[half][0] + f1q[half][1];
        float muh = Sh * (1.f / 64.f);
        float rsh = rsqrtf(Qh * (1.f / 64.f) - muh * muh + 1e-5f);
        float hn = fmaxf((hv - muh) * rsh * l1g + l1b, 0.f);

        // LN over concat [x1(64), hn(64)], relu, dot lin_W
        float s2 = xv + hn;
        float q2 = xv * xv + hn * hn;
#pragma unroll
        for (int o = 16; o; o >>= 1) {
            s2 += __shfl_xor_sync(0xffffffffu, s2, o);
            q2 += __shfl_xor_sync(0xffffffffu, q2, o);
        }
        if (lane == 0) { f2s[half][wh] = s2; f2q[half][wh] = q2; }
        __syncthreads();
        float S2 = f2s[half][0] + f2s[half][1];
        float Q2 = f2q[half][0] + f2q[half][1];
        float mu2 = S2 * (1.f / 128.f);
        float rs2 = rsqrtf(Q2 * (1.f / 128.f) - mu2 * mu2 + 1e-5f);
        float yx = fmaxf((xv - mu2) * rs2 * ngx + nbx, 0.f);
        float yh = fmaxf((hn - mu2) * rs2 * ngh + nbh, 0.f);
        float d = yx * lwx + yh * lwh;
#pragma unroll
        for (int o = 16; o; o >>= 1) d += __shfl_xor_sync(0xffffffffu, d, o);
        if (lane == 0) fd[half][wh] = d;
        __syncthreads();
        if (oc == 0) out[r0 + half] = fd[half][0] + fd[half][1] + lbv;
    }

    // re-zero counters / lookback state for the next run
    for (int i = blockIdx.x * blockDim.x + tid; i < NN; i += gridDim.x * blockDim.x)
        g_cnt[i] = 0;
    {
        int i = blockIdx.x * blockDim.x + tid;
        if (i < SCAN_NBLK) *((unsigned long long*)&g_state[i]) = 0ULL;
    }
}

// ---------------- launch ----------------
extern "C" void kernel_launch(void* const* d_in, const int* in_sizes, int n_in,
                              void* d_out, int out_size) {
    const float* x    = (const float*)d_in[0];
    const void*  ei   = d_in[1];
    const float* encW = (const float*)d_in[2];
    const float* encB = (const float*)d_in[3];
    const float* t    = (const float*)d_in[4];
    const float* W1   = (const float*)d_in[5];
    const float* b1   = (const float*)d_in[6];
    const float* g1   = (const float*)d_in[7];
    const float* be1  = (const float*)d_in[8];
    const float* W2   = (const float*)d_in[9];
    const float* b2   = (const float*)d_in[10];
    const float* ln1g = (const float*)d_in[11];
    const float* ln1b = (const float*)d_in[12];
    const float* ng   = (const float*)d_in[13];
    const float* nb   = (const float*)d_in[14];
    const float* lw   = (const float*)d_in[15];
    const float* lb   = (const float*)d_in[16];
    float* out = (float*)d_out;

    const int AGG_BLOCKS = (NN * 32 + 255) / 256;
    const int MLP_BLOCKS = 296;   // 2 blocks/SM (reg-limited), one balanced wave

    count_kernel<<<EDGE_BLOCKS, 256>>>((const int*)ei);
    scan_lb_kernel<<<SCAN_NBLK, 256>>>();
    scatter_kernel<<<EDGE_BLOCKS, 256>>>((const int*)ei);
    encoder_kernel<<<ENC_BLOCKS, 256>>>(x, encW, encB);
    agg_kernel<<<AGG_BLOCKS, 256>>>(0, t);
    mlp1_kernel<<<MLP_BLOCKS, 128>>>(W1, b1, g1, be1, W2, b2);   // 6th launch -> ncu
    agg_kernel<<<AGG_BLOCKS, 256>>>(1, t);
    mlp2_final_kernel<<<MLP_BLOCKS, 128>>>(W1, b1, g1, be1, W2, b2,
                                           ln1g, ln1b, ng, nb, lw, lb, out);
}

// round 6
// speedup vs baseline: 1.2471x; 1.2471x over previous
#include <cuda_runtime.h>

#define NN 50000
#define EE 800000
#define FIN 128
#define HH 64
#define HX 128   // 2H

#define MSG_EPS 1e-7f
#define SCAN_NBLK ((NN + 255) / 256)   // 196
#define EDGE_BLOCKS ((EE + 255) / 256) // 3125

// ---------------- device scratch (no allocation allowed) ----------------
__device__ int   g_srcSorted[EE];
__device__ int   g_cnt[NN];            // must be 0 at run start (zeroed at run end)
__device__ int   g_off[NN + 1];
__device__ int   g_cursor[NN];
__device__ volatile unsigned long long g_state[SCAN_NBLK];  // lookback state, 0 at start
__device__ float g_xenc[NN * HH];
__device__ float g_tmp[NN * HH];   // agg + residual (gen_conv "out")
__device__ float g_x1[NN * HH];    // conv1 output

// -------- inline dtype detect helper (first 512 words of edge_index) ------
__device__ __forceinline__ int detect_is64(const int* __restrict__ ei32,
                                           int t, int* s_flag) {
    int v = ei32[2 * (t & 255) + 1];
    int any = __syncthreads_or(v != 0);
    if (t == 0) *s_flag = !any;
    __syncthreads();
    return *s_flag;
}

__device__ __forceinline__ void decode_edge(const int* __restrict__ ei32,
                                            int is64, int e, int* s, int* d) {
    if (is64) {
        const long long* p = (const long long*)ei32;
        *s = (int)p[e];
        *d = (int)p[EE + e];
    } else {
        *s = ei32[e];
        *d = ei32[EE + e];
    }
}

// ---------------- count degrees ----------------
__global__ void count_kernel(const int* __restrict__ ei32) {
    __shared__ int s_is64;
    int t = threadIdx.x;
    int is64 = detect_is64(ei32, t, &s_is64);
    int e = blockIdx.x * blockDim.x + t;
    if (e >= EE) return;
    int s, d;
    decode_edge(ei32, is64, e, &s, &d);
    atomicAdd(&g_cnt[d], 1);
}

// ---- block exclusive scan helper ----
__device__ __forceinline__ int block_excl_scan_256(int v, int* wsum, int t) {
    int lane = t & 31;
    int w = t >> 5;
    int incl = v;
#pragma unroll
    for (int o = 1; o < 32; o <<= 1) {
        int n = __shfl_up_sync(0xffffffffu, incl, o);
        if (lane >= o) incl += n;
    }
    if (lane == 31) wsum[w] = incl;
    __syncthreads();
    if (t == 0) {
        int run = 0;
#pragma unroll
        for (int i = 0; i < 8; i++) { int c = wsum[i]; wsum[i] = run; run += c; }
        wsum[8] = run;  // block total
    }
    __syncthreads();
    return incl - v + wsum[w];
}

// ---- single-pass decoupled-lookback scan: g_cnt -> g_off, g_cursor ----
__global__ void scan_lb_kernel() {
    __shared__ int wsum[9];
    __shared__ int s_excl;
    int b = blockIdx.x, t = threadIdx.x;
    int idx = b * 256 + t;
    int v = (idx < NN) ? g_cnt[idx] : 0;
    int excl = block_excl_scan_256(v, wsum, t);
    int total = wsum[8];

    if (t == 0) {
        unsigned long long st = (b == 0)
            ? ((2ULL << 32) | (unsigned)total)
            : ((1ULL << 32) | (unsigned)total);
        atomicExch((unsigned long long*)&g_state[b], st);
        if (b == 0) s_excl = 0;
    }
    if (b > 0 && t < 32) {
        int lane = t;
        int look = b - 1;
        int run = 0;
        while (true) {
            int ip = look - lane;
            unsigned long long s;
            if (ip >= 0) {
                do { s = g_state[ip]; } while ((s >> 32) == 0);
            } else {
                s = (2ULL << 32);
            }
            int isPref = ((s >> 32) == 2u);
            unsigned mask = __ballot_sync(0xffffffffu, isPref);
            int val = (int)(s & 0xffffffffu);
            if (mask) {
                int p = __ffs(mask) - 1;
                int contrib = (lane <= p) ? val : 0;
#pragma unroll
                for (int o = 16; o; o >>= 1) contrib += __shfl_xor_sync(0xffffffffu, contrib, o);
                run += contrib;
                break;
            } else {
                int contrib = val;
#pragma unroll
                for (int o = 16; o; o >>= 1) contrib += __shfl_xor_sync(0xffffffffu, contrib, o);
                run += contrib;
                look -= 32;
            }
        }
        if (lane == 0) {
            s_excl = run;
            atomicExch((unsigned long long*)&g_state[b],
                       (2ULL << 32) | (unsigned)(run + total));
        }
    }
    __syncthreads();
    int base = s_excl;
    if (idx < NN) { int off = excl + base; g_off[idx] = off; g_cursor[idx] = off; }
    if (b == SCAN_NBLK - 1 && t == 0) g_off[NN] = EE;
}

// ---------------- scatter edges into CSR order ----------------
__global__ void scatter_kernel(const int* __restrict__ ei32) {
    __shared__ int s_is64;
    int t = threadIdx.x;
    int is64 = detect_is64(ei32, t, &s_is64);
    int e = blockIdx.x * blockDim.x + t;
    if (e >= EE) return;
    int s, d;
    decode_edge(ei32, is64, e, &s, &d);
    int pos = atomicAdd(&g_cursor[d], 1);
    g_srcSorted[pos] = s;
}

// --------- encoder GEMM: x[N,128] @ W[128,64] + b  (MLP-style) ----------
// 128 threads; thread owns one W column (128 regs); 2 adjacent rows staged
// in smem per iteration; thread (oc, half) computes out[r0+half][oc].
__global__ void __launch_bounds__(128) encoder_kernel(
    const float* __restrict__ x, const float* __restrict__ W,
    const float* __restrict__ b) {
    __shared__ float rowS[2 * FIN];     // 2 rows x 128 features
    int tid = threadIdx.x;
    int oc = tid & 63;
    int half = tid >> 6;

    float wc[FIN];
#pragma unroll
    for (int k = 0; k < FIN; k++) wc[k] = W[k * HH + oc];
    float bv = b[oc];

    const int NPAIR = NN / 2;
    for (int p = blockIdx.x; p < NPAIR; p += gridDim.x) {
        int r0 = 2 * p;
        __syncthreads();
        rowS[tid]       = x[(size_t)r0 * FIN + tid];
        rowS[128 + tid] = x[(size_t)r0 * FIN + 128 + tid];
        __syncthreads();

        float a0 = 0.f, a1 = 0.f, a2 = 0.f, a3 = 0.f;
        const float4* r4 = (const float4*)&rowS[half * FIN];
#pragma unroll
        for (int k4 = 0; k4 < FIN / 4; k4 += 4) {
            float4 va = r4[k4];
            float4 vb = r4[k4 + 1];
            float4 vc = r4[k4 + 2];
            float4 vd = r4[k4 + 3];
            a0 += va.x * wc[4 * k4]      + va.y * wc[4 * k4 + 1]
                + va.z * wc[4 * k4 + 2]  + va.w * wc[4 * k4 + 3];
            a1 += vb.x * wc[4 * k4 + 4]  + vb.y * wc[4 * k4 + 5]
                + vb.z * wc[4 * k4 + 6]  + vb.w * wc[4 * k4 + 7];
            a2 += vc.x * wc[4 * k4 + 8]  + vc.y * wc[4 * k4 + 9]
                + vc.z * wc[4 * k4 + 10] + vc.w * wc[4 * k4 + 11];
            a3 += vd.x * wc[4 * k4 + 12] + vd.y * wc[4 * k4 + 13]
                + vd.z * wc[4 * k4 + 14] + vd.w * wc[4 * k4 + 15];
        }
        g_xenc[(size_t)(r0 + half) * HH + oc] = (a0 + a1) + (a2 + a3) + bv;
    }
}

// ---------------- softmax aggregation: warp per dst node ----------------
__global__ void agg_kernel(int sel, const float* __restrict__ tptr) {
    const float* __restrict__ xin = sel ? g_x1 : g_xenc;
    int gw = (blockIdx.x * blockDim.x + threadIdx.x) >> 5;
    int lane = threadIdx.x & 31;
    if (gw >= NN) return;
    float t = *tptr;
    int e0 = g_off[gw], e1 = g_off[gw + 1];

    float S0 = 0.f, S1 = 0.f, A0 = 0.f, A1 = 0.f;

    int e = e0;
    for (; e + 4 <= e1; e += 4) {
        int s0 = g_srcSorted[e];
        int s1 = g_srcSorted[e + 1];
        int s2 = g_srcSorted[e + 2];
        int s3 = g_srcSorted[e + 3];
        float a0 = xin[(size_t)s0 * HH + lane];
        float b0 = xin[(size_t)s0 * HH + 32 + lane];
        float a1 = xin[(size_t)s1 * HH + lane];
        float b1 = xin[(size_t)s1 * HH + 32 + lane];
        float a2 = xin[(size_t)s2 * HH + lane];
        float b2 = xin[(size_t)s2 * HH + 32 + lane];
        float a3 = xin[(size_t)s3 * HH + lane];
        float b3 = xin[(size_t)s3 * HH + 32 + lane];

        float m, ex;
        m = fmaxf(a0, 0.f) + MSG_EPS; ex = __expf(m * t); S0 += ex; A0 += m * ex;
        m = fmaxf(b0, 0.f) + MSG_EPS; ex = __expf(m * t); S1 += ex; A1 += m * ex;
        m = fmaxf(a1, 0.f) + MSG_EPS; ex = __expf(m * t); S0 += ex; A0 += m * ex;
        m = fmaxf(b1, 0.f) + MSG_EPS; ex = __expf(m * t); S1 += ex; A1 += m * ex;
        m = fmaxf(a2, 0.f) + MSG_EPS; ex = __expf(m * t); S0 += ex; A0 += m * ex;
        m = fmaxf(b2, 0.f) + MSG_EPS; ex = __expf(m * t); S1 += ex; A1 += m * ex;
        m = fmaxf(a3, 0.f) + MSG_EPS; ex = __expf(m * t); S0 += ex; A0 += m * ex;
        m = fmaxf(b3, 0.f) + MSG_EPS; ex = __expf(m * t); S1 += ex; A1 += m * ex;
    }
    for (; e < e1; e++) {
        int s = g_srcSorted[e];
        float a = xin[(size_t)s * HH + lane];
        float b = xin[(size_t)s * HH + 32 + lane];
        float m, ex;
        m = fmaxf(a, 0.f) + MSG_EPS; ex = __expf(m * t); S0 += ex; A0 += m * ex;
        m = fmaxf(b, 0.f) + MSG_EPS; ex = __expf(m * t); S1 += ex; A1 += m * ex;
    }
    float r0 = A0 / (S0 + 1e-16f);
    float r1 = A1 / (S1 + 1e-16f);
    g_tmp[(size_t)gw * HH + lane]      = r0 + xin[(size_t)gw * HH + lane];
    g_tmp[(size_t)gw * HH + 32 + lane] = r1 + xin[(size_t)gw * HH + 32 + lane];
}

// ---------------- fused MLP (conv1): relu(LN(row@W1+b1)) @ W2 + b2 -> g_x1 --
__global__ void __launch_bounds__(128) mlp1_kernel(
    const float* __restrict__ W1, const float* __restrict__ b1,
    const float* __restrict__ g1, const float* __restrict__ be1,
    const float* __restrict__ W2, const float* __restrict__ b2) {
    __shared__ float rowS[2 * HH];
    __shared__ float hS[2][HX];
    __shared__ float part[2][HX];
    __shared__ float sred[2][4], qred[2][4];

    int tid = threadIdx.x;
    int lane = tid & 31;
    int w = tid >> 5;
    int oc = tid & 63;
    int half = tid >> 6;

    float w1c[HH];
#pragma unroll
    for (int k = 0; k < HH; k++) w1c[k] = W1[k * HX + tid];
    float b1v = b1[tid], g1v = g1[tid], be1v = be1[tid];
    float w2c[64];
#pragma unroll
    for (int k = 0; k < 64; k++) w2c[k] = W2[(half * 64 + k) * HH + oc];
    float b2v = b2[oc];

    const int NPAIR = NN / 2;
    for (int p = blockIdx.x; p < NPAIR; p += gridDim.x) {
        int r0 = 2 * p;
        __syncthreads();
        rowS[tid] = g_tmp[(size_t)r0 * HH + tid];
        __syncthreads();

        float h0 = b1v, h1 = b1v;
        const float4* r4 = (const float4*)rowS;
#pragma unroll
        for (int k4 = 0; k4 < HH / 4; k4++) {
            float4 a = r4[k4];
            float4 b = r4[HH / 4 + k4];
            h0 += a.x * w1c[4 * k4] + a.y * w1c[4 * k4 + 1]
                + a.z * w1c[4 * k4 + 2] + a.w * w1c[4 * k4 + 3];
            h1 += b.x * w1c[4 * k4] + b.y * w1c[4 * k4 + 1]
                + b.z * w1c[4 * k4 + 2] + b.w * w1c[4 * k4 + 3];
        }
        float s0 = h0, q0 = h0 * h0, s1 = h1, q1 = h1 * h1;
#pragma unroll
        for (int o = 16; o; o >>= 1) {
            s0 += __shfl_xor_sync(0xffffffffu, s0, o);
            q0 += __shfl_xor_sync(0xffffffffu, q0, o);
            s1 += __shfl_xor_sync(0xffffffffu, s1, o);
            q1 += __shfl_xor_sync(0xffffffffu, q1, o);
        }
        if (lane == 0) { sred[0][w] = s0; qred[0][w] = q0; sred[1][w] = s1; qred[1][w] = q1; }
        __syncthreads();
        float S0 = sred[0][0] + sred[0][1] + sred[0][2] + sred[0][3];
        float Q0 = qred[0][0] + qred[0][1] + qred[0][2] + qred[0][3];
        float S1 = sred[1][0] + sred[1][1] + sred[1][2] + sred[1][3];
        float Q1 = qred[1][0] + qred[1][1] + qred[1][2] + qred[1][3];
        float mu0 = S0 * (1.f / HX);
        float mu1 = S1 * (1.f / HX);
        float rs0 = rsqrtf(Q0 * (1.f / HX) - mu0 * mu0 + 1e-5f);
        float rs1 = rsqrtf(Q1 * (1.f / HX) - mu1 * mu1 + 1e-5f);
        hS[0][tid] = fmaxf((h0 - mu0) * rs0 * g1v + be1v, 0.f);
        hS[1][tid] = fmaxf((h1 - mu1) * rs1 * g1v + be1v, 0.f);
        __syncthreads();

        float acc0 = 0.f, acc1 = 0.f;
        const float4* h40 = (const float4*)&hS[0][half * 64];
        const float4* h41 = (const float4*)&hS[1][half * 64];
#pragma unroll
        for (int k4 = 0; k4 < 16; k4++) {
            float4 a = h40[k4];
            float4 b = h41[k4];
            acc0 += a.x * w2c[4 * k4] + a.y * w2c[4 * k4 + 1]
                  + a.z * w2c[4 * k4 + 2] + a.w * w2c[4 * k4 + 3];
            acc1 += b.x * w2c[4 * k4] + b.y * w2c[4 * k4 + 1]
                  + b.z * w2c[4 * k4 + 2] + b.w * w2c[4 * k4 + 3];
        }
        part[0][tid] = acc0;
        part[1][tid] = acc1;
        __syncthreads();
        float v = part[half][oc] + part[half][oc + 64] + b2v;
        g_x1[(size_t)(r0 + half) * HH + oc] = v;
    }
}

// ------- conv2 MLP fused with the whole network epilogue -> d_out ---------
__global__ void __launch_bounds__(128) mlp2_final_kernel(
    const float* __restrict__ W1, const float* __restrict__ b1,
    const float* __restrict__ g1, const float* __restrict__ be1,
    const float* __restrict__ W2, const float* __restrict__ b2,
    const float* __restrict__ ln1g, const float* __restrict__ ln1b,
    const float* __restrict__ ng, const float* __restrict__ nb,
    const float* __restrict__ lw, const float* __restrict__ lb,
    float* __restrict__ out) {
    __shared__ float rowS[2 * HH];
    __shared__ float hS[2][HX];
    __shared__ float part[2][HX];
    __shared__ float sred[2][4], qred[2][4];
    __shared__ float f1s[2][2], f1q[2][2];
    __shared__ float f2s[2][2], f2q[2][2];
    __shared__ float fd[2][2];

    int tid = threadIdx.x;
    int lane = tid & 31;
    int w = tid >> 5;
    int oc = tid & 63;
    int half = tid >> 6;
    int wh = w & 1;

    float w1c[HH];
#pragma unroll
    for (int k = 0; k < HH; k++) w1c[k] = W1[k * HX + tid];
    float b1v = b1[tid], g1v = g1[tid], be1v = be1[tid];
    float w2c[64];
#pragma unroll
    for (int k = 0; k < 64; k++) w2c[k] = W2[(half * 64 + k) * HH + oc];
    float b2v = b2[oc];
    float l1g = ln1g[oc], l1b = ln1b[oc];
    float ngx = ng[oc], nbx = nb[oc];
    float ngh = ng[64 + oc], nbh = nb[64 + oc];
    float lwx = lw[oc], lwh = lw[64 + oc];
    float lbv = lb[0];

    const int NPAIR = NN / 2;
    for (int p = blockIdx.x; p < NPAIR; p += gridDim.x) {
        int r0 = 2 * p;
        __syncthreads();
        rowS[tid] = g_tmp[(size_t)r0 * HH + tid];
        __syncthreads();

        float h0 = b1v, h1 = b1v;
        const float4* r4 = (const float4*)rowS;
#pragma unroll
        for (int k4 = 0; k4 < HH / 4; k4++) {
            float4 a = r4[k4];
            float4 b = r4[HH / 4 + k4];
            h0 += a.x * w1c[4 * k4] + a.y * w1c[4 * k4 + 1]
                + a.z * w1c[4 * k4 + 2] + a.w * w1c[4 * k4 + 3];
            h1 += b.x * w1c[4 * k4] + b.y * w1c[4 * k4 + 1]
                + b.z * w1c[4 * k4 + 2] + b.w * w1c[4 * k4 + 3];
        }
        float s0 = h0, q0 = h0 * h0, s1 = h1, q1 = h1 * h1;
#pragma unroll
        for (int o = 16; o; o >>= 1) {
            s0 += __shfl_xor_sync(0xffffffffu, s0, o);
            q0 += __shfl_xor_sync(0xffffffffu, q0, o);
            s1 += __shfl_xor_sync(0xffffffffu, s1, o);
            q1 += __shfl_xor_sync(0xffffffffu, q1, o);
        }
        if (lane == 0) { sred[0][w] = s0; qred[0][w] = q0; sred[1][w] = s1; qred[1][w] = q1; }
        __syncthreads();
        float S0 = sred[0][0] + sred[0][1] + sred[0][2] + sred[0][3];
        float Q0 = qred[0][0] + qred[0][1] + qred[0][2] + qred[0][3];
        float S1 = sred[1][0] + sred[1][1] + sred[1][2] + sred[1][3];
        float Q1 = qred[1][0] + qred[1][1] + qred[1][2] + qred[1][3];
        float mu0 = S0 * (1.f / HX);
        float mu1 = S1 * (1.f / HX);
        float rs0 = rsqrtf(Q0 * (1.f / HX) - mu0 * mu0 + 1e-5f);
        float rs1 = rsqrtf(Q1 * (1.f / HX) - mu1 * mu1 + 1e-5f);
        hS[0][tid] = fmaxf((h0 - mu0) * rs0 * g1v + be1v, 0.f);
        hS[1][tid] = fmaxf((h1 - mu1) * rs1 * g1v + be1v, 0.f);
        __syncthreads();

        float acc0 = 0.f, acc1 = 0.f;
        const float4* h40 = (const float4*)&hS[0][half * 64];
        const float4* h41 = (const float4*)&hS[1][half * 64];
#pragma unroll
        for (int k4 = 0; k4 < 16; k4++) {
            float4 a = h40[k4];
            float4 b = h41[k4];
            acc0 += a.x * w2c[4 * k4] + a.y * w2c[4 * k4 + 1]
                  + a.z * w2c[4 * k4 + 2] + a.w * w2c[4 * k4 + 3];
            acc1 += b.x * w2c[4 * k4] + b.y * w2c[4 * k4 + 1]
                  + b.z * w2c[4 * k4 + 2] + b.w * w2c[4 * k4 + 3];
        }
        part[0][tid] = acc0;
        part[1][tid] = acc1;
        __syncthreads();

        // this thread owns h2 value of (row = r0+half, channel oc)
        float hv = part[half][oc] + part[half][oc + 64] + b2v;
        float xv = g_x1[(size_t)r0 * HH + tid];  // == g_x1[(r0+half)*64 + oc]

        // LN over 64 h-channels, relu
        float s = hv, q = hv * hv;
#pragma unroll
        for (int o = 16; o; o >>= 1) {
            s += __shfl_xor_sync(0xffffffffu, s, o);
            q += __shfl_xor_sync(0xffffffffu, q, o);
        }
        if (lane == 0) { f1s[half][wh] = s; f1q[half][wh] = q; }
        __syncthreads();
        float Sh = f1s[half][0] + f1s[half][1];
        float Qh = f1q[half][0] + f1q[half][1];
        float muh = Sh * (1.f / 64.f);
        float rsh = rsqrtf(Qh * (1.f / 64.f) - muh * muh + 1e-5f);
        float hn = fmaxf((hv - muh) * rsh * l1g + l1b, 0.f);

        // LN over concat [x1(64), hn(64)], relu, dot lin_W
        float s2 = xv + hn;
        float q2 = xv * xv + hn * hn;
#pragma unroll
        for (int o = 16; o; o >>= 1) {
            s2 += __shfl_xor_sync(0xffffffffu, s2, o);
            q2 += __shfl_xor_sync(0xffffffffu, q2, o);
        }
        if (lane == 0) { f2s[half][wh] = s2; f2q[half][wh] = q2; }
        __syncthreads();
        float S2 = f2s[half][0] + f2s[half][1];
        float Q2 = f2q[half][0] + f2q[half][1];
        float mu2 = S2 * (1.f / 128.f);
        float rs2 = rsqrtf(Q2 * (1.f / 128.f) - mu2 * mu2 + 1e-5f);
        float yx = fmaxf((xv - mu2) * rs2 * ngx + nbx, 0.f);
        float yh = fmaxf((hn - mu2) * rs2 * ngh + nbh, 0.f);
        float d = yx * lwx + yh * lwh;
#pragma unroll
        for (int o = 16; o; o >>= 1) d += __shfl_xor_sync(0xffffffffu, d, o);
        if (lane == 0) fd[half][wh] = d;
        __syncthreads();
        if (oc == 0) out[r0 + half] = fd[half][0] + fd[half][1] + lbv;
    }

    // re-zero counters / lookback state for the next run
    for (int i = blockIdx.x * blockDim.x + tid; i < NN; i += gridDim.x * blockDim.x)
        g_cnt[i] = 0;
    {
        int i = blockIdx.x * blockDim.x + tid;
        if (i < SCAN_NBLK) *((unsigned long long*)&g_state[i]) = 0ULL;
    }
}

// ---------------- launch ----------------
extern "C" void kernel_launch(void* const* d_in, const int* in_sizes, int n_in,
                              void* d_out, int out_size) {
    const float* x    = (const float*)d_in[0];
    const void*  ei   = d_in[1];
    const float* encW = (const float*)d_in[2];
    const float* encB = (const float*)d_in[3];
    const float* t    = (const float*)d_in[4];
    const float* W1   = (const float*)d_in[5];
    const float* b1   = (const float*)d_in[6];
    const float* g1   = (const float*)d_in[7];
    const float* be1  = (const float*)d_in[8];
    const float* W2   = (const float*)d_in[9];
    const float* b2   = (const float*)d_in[10];
    const float* ln1g = (const float*)d_in[11];
    const float* ln1b = (const float*)d_in[12];
    const float* ng   = (const float*)d_in[13];
    const float* nb   = (const float*)d_in[14];
    const float* lw   = (const float*)d_in[15];
    const float* lb   = (const float*)d_in[16];
    float* out = (float*)d_out;

    const int AGG_BLOCKS = (NN * 32 + 255) / 256;
    const int MLP_BLOCKS = 444;   // 3 blocks/SM, one wave

    count_kernel<<<EDGE_BLOCKS, 256>>>((const int*)ei);
    scan_lb_kernel<<<SCAN_NBLK, 256>>>();
    scatter_kernel<<<EDGE_BLOCKS, 256>>>((const int*)ei);
    encoder_kernel<<<MLP_BLOCKS, 128>>>(x, encW, encB);
    agg_kernel<<<AGG_BLOCKS, 256>>>(0, t);
    mlp1_kernel<<<MLP_BLOCKS, 128>>>(W1, b1, g1, be1, W2, b2);
    agg_kernel<<<AGG_BLOCKS, 256>>>(1, t);
    mlp2_final_kernel<<<MLP_BLOCKS, 128>>>(W1, b1, g1, be1, W2, b2,
                                           ln1g, ln1b, ng, nb, lw, lb, out);
}

// round 7
// speedup vs baseline: 1.2890x; 1.0335x over previous
#include <cuda_runtime.h>

#define NN 50000
#define EE 800000
#define FIN 128
#define HH 64
#define HX 128   // 2H

#define MSG_EPS 1e-7f
#define SCAN_NBLK ((NN + 255) / 256)   // 196
#define EDGE_BLOCKS ((EE + 255) / 256) // 3125

// ---------------- device scratch (no allocation allowed) ----------------
__device__ int   g_srcSorted[EE];
__device__ int   g_cnt[NN];            // must be 0 at run start (zeroed at run end)
__device__ int   g_off[NN + 1];
__device__ int   g_cursor[NN];
__device__ volatile unsigned long long g_state[SCAN_NBLK];  // lookback state, 0 at start
__device__ float g_xenc[NN * HH];
__device__ float g_tmp[NN * HH];   // agg + residual (gen_conv "out")
__device__ float g_x1[NN * HH];    // conv1 output

// -------- inline dtype detect helper (first 512 words of edge_index) ------
__device__ __forceinline__ int detect_is64(const int* __restrict__ ei32,
                                           int t, int* s_flag) {
    int v = ei32[2 * (t & 255) + 1];
    int any = __syncthreads_or(v != 0);
    if (t == 0) *s_flag = !any;
    __syncthreads();
    return *s_flag;
}

__device__ __forceinline__ void decode_edge(const int* __restrict__ ei32,
                                            int is64, int e, int* s, int* d) {
    if (is64) {
        const long long* p = (const long long*)ei32;
        *s = (int)p[e];
        *d = (int)p[EE + e];
    } else {
        *s = ei32[e];
        *d = ei32[EE + e];
    }
}

// ---------------- count degrees ----------------
__global__ void count_kernel(const int* __restrict__ ei32) {
    __shared__ int s_is64;
    int t = threadIdx.x;
    int is64 = detect_is64(ei32, t, &s_is64);
    int e = blockIdx.x * blockDim.x + t;
    if (e >= EE) return;
    int s, d;
    decode_edge(ei32, is64, e, &s, &d);
    atomicAdd(&g_cnt[d], 1);
}

// ---- block exclusive scan helper ----
__device__ __forceinline__ int block_excl_scan_256(int v, int* wsum, int t) {
    int lane = t & 31;
    int w = t >> 5;
    int incl = v;
#pragma unroll
    for (int o = 1; o < 32; o <<= 1) {
        int n = __shfl_up_sync(0xffffffffu, incl, o);
        if (lane >= o) incl += n;
    }
    if (lane == 31) wsum[w] = incl;
    __syncthreads();
    if (t == 0) {
        int run = 0;
#pragma unroll
        for (int i = 0; i < 8; i++) { int c = wsum[i]; wsum[i] = run; run += c; }
        wsum[8] = run;  // block total
    }
    __syncthreads();
    return incl - v + wsum[w];
}

// ---- single-pass decoupled-lookback scan: g_cnt -> g_off, g_cursor ----
__global__ void scan_lb_kernel() {
    __shared__ int wsum[9];
    __shared__ int s_excl;
    int b = blockIdx.x, t = threadIdx.x;
    int idx = b * 256 + t;
    int v = (idx < NN) ? g_cnt[idx] : 0;
    int excl = block_excl_scan_256(v, wsum, t);
    int total = wsum[8];

    if (t == 0) {
        unsigned long long st = (b == 0)
            ? ((2ULL << 32) | (unsigned)total)
            : ((1ULL << 32) | (unsigned)total);
        atomicExch((unsigned long long*)&g_state[b], st);
        if (b == 0) s_excl = 0;
    }
    if (b > 0 && t < 32) {
        int lane = t;
        int look = b - 1;
        int run = 0;
        while (true) {
            int ip = look - lane;
            unsigned long long s;
            if (ip >= 0) {
                do { s = g_state[ip]; } while ((s >> 32) == 0);
            } else {
                s = (2ULL << 32);
            }
            int isPref = ((s >> 32) == 2u);
            unsigned mask = __ballot_sync(0xffffffffu, isPref);
            int val = (int)(s & 0xffffffffu);
            if (mask) {
                int p = __ffs(mask) - 1;
                int contrib = (lane <= p) ? val : 0;
#pragma unroll
                for (int o = 16; o; o >>= 1) contrib += __shfl_xor_sync(0xffffffffu, contrib, o);
                run += contrib;
                break;
            } else {
                int contrib = val;
#pragma unroll
                for (int o = 16; o; o >>= 1) contrib += __shfl_xor_sync(0xffffffffu, contrib, o);
                run += contrib;
                look -= 32;
            }
        }
        if (lane == 0) {
            s_excl = run;
            atomicExch((unsigned long long*)&g_state[b],
                       (2ULL << 32) | (unsigned)(run + total));
        }
    }
    __syncthreads();
    int base = s_excl;
    if (idx < NN) { int off = excl + base; g_off[idx] = off; g_cursor[idx] = off; }
    if (b == SCAN_NBLK - 1 && t == 0) g_off[NN] = EE;
}

// ---------------- scatter edges into CSR order ----------------
__global__ void scatter_kernel(const int* __restrict__ ei32) {
    __shared__ int s_is64;
    int t = threadIdx.x;
    int is64 = detect_is64(ei32, t, &s_is64);
    int e = blockIdx.x * blockDim.x + t;
    if (e >= EE) return;
    int s, d;
    decode_edge(ei32, is64, e, &s, &d);
    int pos = atomicAdd(&g_cursor[d], 1);
    g_srcSorted[pos] = s;
}

// --------- encoder GEMM: x[N,128] @ W[128,64] + b  (8 rows / iteration) ---
// 128 threads; thread owns one W column (128 regs). Per iteration: stage 8
// rows (1024 floats) in smem, each half computes 4 row-dots (ILP-4).
__global__ void __launch_bounds__(128) encoder_kernel(
    const float* __restrict__ x, const float* __restrict__ W,
    const float* __restrict__ b) {
    __shared__ float rowS[8 * FIN];     // 4 KB
    int tid = threadIdx.x;
    int oc = tid & 63;
    int half = tid >> 6;

    float wc[FIN];
#pragma unroll
    for (int k = 0; k < FIN; k++) wc[k] = W[k * HH + oc];
    float bv = b[oc];

    const int NOCT = NN / 8;   // 6250
    for (int p = blockIdx.x; p < NOCT; p += gridDim.x) {
        int r0 = 8 * p;
        __syncthreads();
        const float4* xg = (const float4*)(x + (size_t)r0 * FIN);
        float4* s4 = (float4*)rowS;
        s4[tid]       = xg[tid];        // rows r0..r0+3
        s4[128 + tid] = xg[128 + tid];  // rows r0+4..r0+7
        __syncthreads();

        int rbase = half * 4;
        const float4* q0 = (const float4*)&rowS[(rbase + 0) * FIN];
        const float4* q1 = (const float4*)&rowS[(rbase + 1) * FIN];
        const float4* q2 = (const float4*)&rowS[(rbase + 2) * FIN];
        const float4* q3 = (const float4*)&rowS[(rbase + 3) * FIN];
        float a0 = 0.f, a1 = 0.f, a2 = 0.f, a3 = 0.f;
#pragma unroll
        for (int k4 = 0; k4 < FIN / 4; k4++) {
            float4 v0 = q0[k4];
            float4 v1 = q1[k4];
            float4 v2 = q2[k4];
            float4 v3 = q3[k4];
            int k = 4 * k4;
            a0 += v0.x * wc[k] + v0.y * wc[k + 1] + v0.z * wc[k + 2] + v0.w * wc[k + 3];
            a1 += v1.x * wc[k] + v1.y * wc[k + 1] + v1.z * wc[k + 2] + v1.w * wc[k + 3];
            a2 += v2.x * wc[k] + v2.y * wc[k + 1] + v2.z * wc[k + 2] + v2.w * wc[k + 3];
            a3 += v3.x * wc[k] + v3.y * wc[k + 1] + v3.z * wc[k + 2] + v3.w * wc[k + 3];
        }
        size_t ob = (size_t)(r0 + rbase) * HH + oc;
        g_xenc[ob]          = a0 + bv;
        g_xenc[ob + HH]     = a1 + bv;
        g_xenc[ob + 2 * HH] = a2 + bv;
        g_xenc[ob + 3 * HH] = a3 + bv;
    }
}

// ---------------- softmax aggregation: warp per dst node ----------------
// Lane owns channel pair {2*lane, 2*lane+1}: one LDG.64 per edge per lane.
__global__ void agg_kernel(int sel, const float* __restrict__ tptr) {
    const float2* __restrict__ xin2 = (const float2*)(sel ? g_x1 : g_xenc);
    int gw = (blockIdx.x * blockDim.x + threadIdx.x) >> 5;
    int lane = threadIdx.x & 31;
    if (gw >= NN) return;
    float t = *tptr;
    int e0 = g_off[gw], e1 = g_off[gw + 1];

    float S0 = 0.f, S1 = 0.f, A0 = 0.f, A1 = 0.f;

    int e = e0;
    for (; e + 4 <= e1; e += 4) {
        int s0 = g_srcSorted[e];
        int s1 = g_srcSorted[e + 1];
        int s2 = g_srcSorted[e + 2];
        int s3 = g_srcSorted[e + 3];
        float2 v0 = xin2[s0 * 32 + lane];
        float2 v1 = xin2[s1 * 32 + lane];
        float2 v2 = xin2[s2 * 32 + lane];
        float2 v3 = xin2[s3 * 32 + lane];

        float m, ex;
        m = fmaxf(v0.x, 0.f) + MSG_EPS; ex = __expf(m * t); S0 += ex; A0 += m * ex;
        m = fmaxf(v0.y, 0.f) + MSG_EPS; ex = __expf(m * t); S1 += ex; A1 += m * ex;
        m = fmaxf(v1.x, 0.f) + MSG_EPS; ex = __expf(m * t); S0 += ex; A0 += m * ex;
        m = fmaxf(v1.y, 0.f) + MSG_EPS; ex = __expf(m * t); S1 += ex; A1 += m * ex;
        m = fmaxf(v2.x, 0.f) + MSG_EPS; ex = __expf(m * t); S0 += ex; A0 += m * ex;
        m = fmaxf(v2.y, 0.f) + MSG_EPS; ex = __expf(m * t); S1 += ex; A1 += m * ex;
        m = fmaxf(v3.x, 0.f) + MSG_EPS; ex = __expf(m * t); S0 += ex; A0 += m * ex;
        m = fmaxf(v3.y, 0.f) + MSG_EPS; ex = __expf(m * t); S1 += ex; A1 += m * ex;
    }
    for (; e < e1; e++) {
        int s = g_srcSorted[e];
        float2 v = xin2[s * 32 + lane];
        float m, ex;
        m = fmaxf(v.x, 0.f) + MSG_EPS; ex = __expf(m * t); S0 += ex; A0 += m * ex;
        m = fmaxf(v.y, 0.f) + MSG_EPS; ex = __expf(m * t); S1 += ex; A1 += m * ex;
    }
    float2 self = xin2[gw * 32 + lane];
    float2 o;
    o.x = A0 / (S0 + 1e-16f) + self.x;
    o.y = A1 / (S1 + 1e-16f) + self.y;
    ((float2*)g_tmp)[gw * 32 + lane] = o;
}

// ---------------- fused MLP (conv1): relu(LN(row@W1+b1)) @ W2 + b2 -> g_x1 --
__global__ void __launch_bounds__(128) mlp1_kernel(
    const float* __restrict__ W1, const float* __restrict__ b1,
    const float* __restrict__ g1, const float* __restrict__ be1,
    const float* __restrict__ W2, const float* __restrict__ b2) {
    __shared__ float rowS[2 * HH];
    __shared__ float hS[2][HX];
    __shared__ float part[2][HX];
    __shared__ float sred[2][4], qred[2][4];

    int tid = threadIdx.x;
    int lane = tid & 31;
    int w = tid >> 5;
    int oc = tid & 63;
    int half = tid >> 6;

    float w1c[HH];
#pragma unroll
    for (int k = 0; k < HH; k++) w1c[k] = W1[k * HX + tid];
    float b1v = b1[tid], g1v = g1[tid], be1v = be1[tid];
    float w2c[64];
#pragma unroll
    for (int k = 0; k < 64; k++) w2c[k] = W2[(half * 64 + k) * HH + oc];
    float b2v = b2[oc];

    const int NPAIR = NN / 2;
    for (int p = blockIdx.x; p < NPAIR; p += gridDim.x) {
        int r0 = 2 * p;
        __syncthreads();
        rowS[tid] = g_tmp[(size_t)r0 * HH + tid];
        __syncthreads();

        float h0 = b1v, h1 = b1v;
        const float4* r4 = (const float4*)rowS;
#pragma unroll
        for (int k4 = 0; k4 < HH / 4; k4++) {
            float4 a = r4[k4];
            float4 b = r4[HH / 4 + k4];
            h0 += a.x * w1c[4 * k4] + a.y * w1c[4 * k4 + 1]
                + a.z * w1c[4 * k4 + 2] + a.w * w1c[4 * k4 + 3];
            h1 += b.x * w1c[4 * k4] + b.y * w1c[4 * k4 + 1]
                + b.z * w1c[4 * k4 + 2] + b.w * w1c[4 * k4 + 3];
        }
        float s0 = h0, q0 = h0 * h0, s1 = h1, q1 = h1 * h1;
#pragma unroll
        for (int o = 16; o; o >>= 1) {
            s0 += __shfl_xor_sync(0xffffffffu, s0, o);
            q0 += __shfl_xor_sync(0xffffffffu, q0, o);
            s1 += __shfl_xor_sync(0xffffffffu, s1, o);
            q1 += __shfl_xor_sync(0xffffffffu, q1, o);
        }
        if (lane == 0) { sred[0][w] = s0; qred[0][w] = q0; sred[1][w] = s1; qred[1][w] = q1; }
        __syncthreads();
        float S0 = sred[0][0] + sred[0][1] + sred[0][2] + sred[0][3];
        float Q0 = qred[0][0] + qred[0][1] + qred[0][2] + qred[0][3];
        float S1 = sred[1][0] + sred[1][1] + sred[1][2] + sred[1][3];
        float Q1 = qred[1][0] + qred[1][1] + qred[1][2] + qred[1][3];
        float mu0 = S0 * (1.f / HX);
        float mu1 = S1 * (1.f / HX);
        float rs0 = rsqrtf(Q0 * (1.f / HX) - mu0 * mu0 + 1e-5f);
        float rs1 = rsqrtf(Q1 * (1.f / HX) - mu1 * mu1 + 1e-5f);
        hS[0][tid] = fmaxf((h0 - mu0) * rs0 * g1v + be1v, 0.f);
        hS[1][tid] = fmaxf((h1 - mu1) * rs1 * g1v + be1v, 0.f);
        __syncthreads();

        float acc0 = 0.f, acc1 = 0.f;
        const float4* h40 = (const float4*)&hS[0][half * 64];
        const float4* h41 = (const float4*)&hS[1][half * 64];
#pragma unroll
        for (int k4 = 0; k4 < 16; k4++) {
            float4 a = h40[k4];
            float4 b = h41[k4];
            acc0 += a.x * w2c[4 * k4] + a.y * w2c[4 * k4 + 1]
                  + a.z * w2c[4 * k4 + 2] + a.w * w2c[4 * k4 + 3];
            acc1 += b.x * w2c[4 * k4] + b.y * w2c[4 * k4 + 1]
                  + b.z * w2c[4 * k4 + 2] + b.w * w2c[4 * k4 + 3];
        }
        part[0][tid] = acc0;
        part[1][tid] = acc1;
        __syncthreads();
        float v = part[half][oc] + part[half][oc + 64] + b2v;
        g_x1[(size_t)(r0 + half) * HH + oc] = v;
    }
}

// ------- conv2 MLP fused with the whole network epilogue -> d_out ---------
__global__ void __launch_bounds__(128) mlp2_final_kernel(
    const float* __restrict__ W1, const float* __restrict__ b1,
    const float* __restrict__ g1, const float* __restrict__ be1,
    const float* __restrict__ W2, const float* __restrict__ b2,
    const float* __restrict__ ln1g, const float* __restrict__ ln1b,
    const float* __restrict__ ng, const float* __restrict__ nb,
    const float* __restrict__ lw, const float* __restrict__ lb,
    float* __restrict__ out) {
    __shared__ float rowS[2 * HH];
    __shared__ float hS[2][HX];
    __shared__ float part[2][HX];
    __shared__ float sred[2][4], qred[2][4];
    __shared__ float f1s[2][2], f1q[2][2];
    __shared__ float f2s[2][2], f2q[2][2];
    __shared__ float fd[2][2];

    int tid = threadIdx.x;
    int lane = tid & 31;
    int w = tid >> 5;
    int oc = tid & 63;
    int half = tid >> 6;
    int wh = w & 1;

    float w1c[HH];
#pragma unroll
    for (int k = 0; k < HH; k++) w1c[k] = W1[k * HX + tid];
    float b1v = b1[tid], g1v = g1[tid], be1v = be1[tid];
    float w2c[64];
#pragma unroll
    for (int k = 0; k < 64; k++) w2c[k] = W2[(half * 64 + k) * HH + oc];
    float b2v = b2[oc];
    float l1g = ln1g[oc], l1b = ln1b[oc];
    float ngx = ng[oc], nbx = nb[oc];
    float ngh = ng[64 + oc], nbh = nb[64 + oc];
    float lwx = lw[oc], lwh = lw[64 + oc];
    float lbv = lb[0];

    const int NPAIR = NN / 2;
    for (int p = blockIdx.x; p < NPAIR; p += gridDim.x) {
        int r0 = 2 * p;
        __syncthreads();
        rowS[tid] = g_tmp[(size_t)r0 * HH + tid];
        __syncthreads();

        float h0 = b1v, h1 = b1v;
        const float4* r4 = (const float4*)rowS;
#pragma unroll
        for (int k4 = 0; k4 < HH / 4; k4++) {
            float4 a = r4[k4];
            float4 b = r4[HH / 4 + k4];
            h0 += a.x * w1c[4 * k4] + a.y * w1c[4 * k4 + 1]
                + a.z * w1c[4 * k4 + 2] + a.w * w1c[4 * k4 + 3];
            h1 += b.x * w1c[4 * k4] + b.y * w1c[4 * k4 + 1]
                + b.z * w1c[4 * k4 + 2] + b.w * w1c[4 * k4 + 3];
        }
        float s0 = h0, q0 = h0 * h0, s1 = h1, q1 = h1 * h1;
#pragma unroll
        for (int o = 16; o; o >>= 1) {
            s0 += __shfl_xor_sync(0xffffffffu, s0, o);
            q0 += __shfl_xor_sync(0xffffffffu, q0, o);
            s1 += __shfl_xor_sync(0xffffffffu, s1, o);
            q1 += __shfl_xor_sync(0xffffffffu, q1, o);
        }
        if (lane == 0) { sred[0][w] = s0; qred[0][w] = q0; sred[1][w] = s1; qred[1][w] = q1; }
        __syncthreads();
        float S0 = sred[0][0] + sred[0][1] + sred[0][2] + sred[0][3];
        float Q0 = qred[0][0] + qred[0][1] + qred[0][2] + qred[0][3];
        float S1 = sred[1][0] + sred[1][1] + sred[1][2] + sred[1][3];
        float Q1 = qred[1][0] + qred[1][1] + qred[1][2] + qred[1][3];
        float mu0 = S0 * (1.f / HX);
        float mu1 = S1 * (1.f / HX);
        float rs0 = rsqrtf(Q0 * (1.f / HX) - mu0 * mu0 + 1e-5f);
        float rs1 = rsqrtf(Q1 * (1.f / HX) - mu1 * mu1 + 1e-5f);
        hS[0][tid] = fmaxf((h0 - mu0) * rs0 * g1v + be1v, 0.f);
        hS[1][tid] = fmaxf((h1 - mu1) * rs1 * g1v + be1v, 0.f);
        __syncthreads();

        float acc0 = 0.f, acc1 = 0.f;
        const float4* h40 = (const float4*)&hS[0][half * 64];
        const float4* h41 = (const float4*)&hS[1][half * 64];
#pragma unroll
        for (int k4 = 0; k4 < 16; k4++) {
            float4 a = h40[k4];
            float4 b = h41[k4];
            acc0 += a.x * w2c[4 * k4] + a.y * w2c[4 * k4 + 1]
                  + a.z * w2c[4 * k4 + 2] + a.w * w2c[4 * k4 + 3];
            acc1 += b.x * w2c[4 * k4] + b.y * w2c[4 * k4 + 1]
                  + b.z * w2c[4 * k4 + 2] + b.w * w2c[4 * k4 + 3];
        }
        part[0][tid] = acc0;
        part[1][tid] = acc1;
        __syncthreads();

        // this thread owns h2 value of (row = r0+half, channel oc)
        float hv = part[half][oc] + part[half][oc + 64] + b2v;
        float xv = g_x1[(size_t)r0 * HH + tid];  // == g_x1[(r0+half)*64 + oc]

        // LN over 64 h-channels, relu
        float s = hv, q = hv * hv;
#pragma unroll
        for (int o = 16; o; o >>= 1) {
            s += __shfl_xor_sync(0xffffffffu, s, o);
            q += __shfl_xor_sync(0xffffffffu, q, o);
        }
        if (lane == 0) { f1s[half][wh] = s; f1q[half][wh] = q; }
        __syncthreads();
        float Sh = f1s[half][0] + f1s[half][1];
        float Qh = f1q[half][0] + f1q[half][1];
        float muh = Sh * (1.f / 64.f);
        float rsh = rsqrtf(Qh * (1.f / 64.f) - muh * muh + 1e-5f);
        float hn = fmaxf((hv - muh) * rsh * l1g + l1b, 0.f);

        // LN over concat [x1(64), hn(64)], relu, dot lin_W
        float s2 = xv + hn;
        float q2 = xv * xv + hn * hn;
#pragma unroll
        for (int o = 16; o; o >>= 1) {
            s2 += __shfl_xor_sync(0xffffffffu, s2, o);
            q2 += __shfl_xor_sync(0xffffffffu, q2, o);
        }
        if (lane == 0) { f2s[half][wh] = s2; f2q[half][wh] = q2; }
        __syncthreads();
        float S2 = f2s[half][0] + f2s[half][1];
        float Q2 = f2q[half][0] + f2q[half][1];
        float mu2 = S2 * (1.f / 128.f);
        float rs2 = rsqrtf(Q2 * (1.f / 128.f) - mu2 * mu2 + 1e-5f);
        float yx = fmaxf((xv - mu2) * rs2 * ngx + nbx, 0.f);
        float yh = fmaxf((hn - mu2) * rs2 * ngh + nbh, 0.f);
        float d = yx * lwx + yh * lwh;
#pragma unroll
        for (int o = 16; o; o >>= 1) d += __shfl_xor_sync(0xffffffffu, d, o);
        if (lane == 0) fd[half][wh] = d;
        __syncthreads();
        if (oc == 0) out[r0 + half] = fd[half][0] + fd[half][1] + lbv;
    }

    // re-zero counters / lookback state for the next run
    for (int i = blockIdx.x * blockDim.x + tid; i < NN; i += gridDim.x * blockDim.x)
        g_cnt[i] = 0;
    {
        int i = blockIdx.x * blockDim.x + tid;
        if (i < SCAN_NBLK) *((unsigned long long*)&g_state[i]) = 0ULL;
    }
}

// ---------------- launch ----------------
extern "C" void kernel_launch(void* const* d_in, const int* in_sizes, int n_in,
                              void* d_out, int out_size) {
    const float* x    = (const float*)d_in[0];
    const void*  ei   = d_in[1];
    const float* encW = (const float*)d_in[2];
    const float* encB = (const float*)d_in[3];
    const float* t    = (const float*)d_in[4];
    const float* W1   = (const float*)d_in[5];
    const float* b1   = (const float*)d_in[6];
    const float* g1   = (const float*)d_in[7];
    const float* be1  = (const float*)d_in[8];
    const float* W2   = (const float*)d_in[9];
    const float* b2   = (const float*)d_in[10];
    const float* ln1g = (const float*)d_in[11];
    const float* ln1b = (const float*)d_in[12];
    const float* ng   = (const float*)d_in[13];
    const float* nb   = (const float*)d_in[14];
    const float* lw   = (const float*)d_in[15];
    const float* lb   = (const float*)d_in[16];
    float* out = (float*)d_out;

    const int AGG_BLOCKS = (NN * 32 + 255) / 256;
    const int MLP_BLOCKS = 444;   // 3 blocks/SM, one wave

    count_kernel<<<EDGE_BLOCKS, 256>>>((const int*)ei);
    scan_lb_kernel<<<SCAN_NBLK, 256>>>();
    scatter_kernel<<<EDGE_BLOCKS, 256>>>((const int*)ei);
    encoder_kernel<<<MLP_BLOCKS, 128>>>(x, encW, encB);
    agg_kernel<<<AGG_BLOCKS, 256>>>(0, t);
    mlp1_kernel<<<MLP_BLOCKS, 128>>>(W1, b1, g1, be1, W2, b2);
    agg_kernel<<<AGG_BLOCKS, 256>>>(1, t);
    mlp2_final_kernel<<<MLP_BLOCKS, 128>>>(W1, b1, g1, be1, W2, b2,
                                           ln1g, ln1b, ng, nb, lw, lb, out);
}

// round 8
// speedup vs baseline: 2.1038x; 1.6321x over previous
#include <cuda_runtime.h>

#define NN 50000
#define EE 800000
#define FIN 128
#define HH 64
#define HX 128   // 2H

#define MSG_EPS 1e-7f
#define SCAN_NBLK ((NN + 255) / 256)   // 196
#define EDGE_BLOCKS ((EE + 255) / 256) // 3125
#define NTILES ((NN + 31) / 32)        // 1563

// ---------------- device scratch (no allocation allowed) ----------------
__device__ int   g_srcSorted[EE];
__device__ int   g_cnt[NN];            // 0 at run start (zeroed at run end)
__device__ int   g_off[NN + 1];
__device__ int   g_cursor[NN];
__device__ volatile unsigned long long g_state[SCAN_NBLK];
__device__ float g_xenc[NN * HH];
__device__ float g_tmp[NN * HH];
__device__ float g_x1[NN * HH];

// ---------------- tf32 mma helpers ----------------
__device__ __forceinline__ unsigned f2tf(float f) {
    unsigned r;
    asm("cvt.rna.tf32.f32 %0, %1;" : "=r"(r) : "f"(f));
    return r;
}
__device__ __forceinline__ void mma8(float& d0, float& d1, float& d2, float& d3,
                                     unsigned a0, unsigned a1, unsigned a2, unsigned a3,
                                     unsigned b0, unsigned b1) {
    asm("mma.sync.aligned.m16n8k8.row.col.f32.tf32.tf32.f32 "
        "{%0,%1,%2,%3},{%4,%5,%6,%7},{%8,%9},{%0,%1,%2,%3};"
        : "+f"(d0), "+f"(d1), "+f"(d2), "+f"(d3)
        : "r"(a0), "r"(a1), "r"(a2), "r"(a3), "r"(b0), "r"(b1));
}

// -------- inline dtype detect helper --------
__device__ __forceinline__ int detect_is64(const int* __restrict__ ei32,
                                           int t, int* s_flag) {
    int v = ei32[2 * (t & 255) + 1];
    int any = __syncthreads_or(v != 0);
    if (t == 0) *s_flag = !any;
    __syncthreads();
    return *s_flag;
}
__device__ __forceinline__ void decode_edge(const int* __restrict__ ei32,
                                            int is64, int e, int* s, int* d) {
    if (is64) {
        const long long* p = (const long long*)ei32;
        *s = (int)p[e];
        *d = (int)p[EE + e];
    } else {
        *s = ei32[e];
        *d = ei32[EE + e];
    }
}

// ---------------- count degrees ----------------
__global__ void count_kernel(const int* __restrict__ ei32) {
    __shared__ int s_is64;
    int t = threadIdx.x;
    int is64 = detect_is64(ei32, t, &s_is64);
    int e = blockIdx.x * blockDim.x + t;
    if (e >= EE) return;
    int s, d;
    decode_edge(ei32, is64, e, &s, &d);
    atomicAdd(&g_cnt[d], 1);
}

// ---- block exclusive scan helper ----
__device__ __forceinline__ int block_excl_scan_256(int v, int* wsum, int t) {
    int lane = t & 31;
    int w = t >> 5;
    int incl = v;
#pragma unroll
    for (int o = 1; o < 32; o <<= 1) {
        int n = __shfl_up_sync(0xffffffffu, incl, o);
        if (lane >= o) incl += n;
    }
    if (lane == 31) wsum[w] = incl;
    __syncthreads();
    if (t == 0) {
        int run = 0;
#pragma unroll
        for (int i = 0; i < 8; i++) { int c = wsum[i]; wsum[i] = run; run += c; }
        wsum[8] = run;
    }
    __syncthreads();
    return incl - v + wsum[w];
}

// ---- single-pass decoupled-lookback scan ----
__global__ void scan_lb_kernel() {
    __shared__ int wsum[9];
    __shared__ int s_excl;
    int b = blockIdx.x, t = threadIdx.x;
    int idx = b * 256 + t;
    int v = (idx < NN) ? g_cnt[idx] : 0;
    int excl = block_excl_scan_256(v, wsum, t);
    int total = wsum[8];

    if (t == 0) {
        unsigned long long st = (b == 0)
            ? ((2ULL << 32) | (unsigned)total)
            : ((1ULL << 32) | (unsigned)total);
        atomicExch((unsigned long long*)&g_state[b], st);
        if (b == 0) s_excl = 0;
    }
    if (b > 0 && t < 32) {
        int lane = t;
        int look = b - 1;
        int run = 0;
        while (true) {
            int ip = look - lane;
            unsigned long long s;
            if (ip >= 0) {
                do { s = g_state[ip]; } while ((s >> 32) == 0);
            } else {
                s = (2ULL << 32);
            }
            int isPref = ((s >> 32) == 2u);
            unsigned mask = __ballot_sync(0xffffffffu, isPref);
            int val = (int)(s & 0xffffffffu);
            if (mask) {
                int p = __ffs(mask) - 1;
                int contrib = (lane <= p) ? val : 0;
#pragma unroll
                for (int o = 16; o; o >>= 1) contrib += __shfl_xor_sync(0xffffffffu, contrib, o);
                run += contrib;
                break;
            } else {
                int contrib = val;
#pragma unroll
                for (int o = 16; o; o >>= 1) contrib += __shfl_xor_sync(0xffffffffu, contrib, o);
                run += contrib;
                look -= 32;
            }
        }
        if (lane == 0) {
            s_excl = run;
            atomicExch((unsigned long long*)&g_state[b],
                       (2ULL << 32) | (unsigned)(run + total));
        }
    }
    __syncthreads();
    int base = s_excl;
    if (idx < NN) { int off = excl + base; g_off[idx] = off; g_cursor[idx] = off; }
    if (b == SCAN_NBLK - 1 && t == 0) g_off[NN] = EE;
}

// ---------------- scatter edges into CSR order ----------------
__global__ void scatter_kernel(const int* __restrict__ ei32) {
    __shared__ int s_is64;
    int t = threadIdx.x;
    int is64 = detect_is64(ei32, t, &s_is64);
    int e = blockIdx.x * blockDim.x + t;
    if (e >= EE) return;
    int s, d;
    decode_edge(ei32, is64, e, &s, &d);
    int pos = atomicAdd(&g_cursor[d], 1);
    g_srcSorted[pos] = s;
}

// --------- encoder GEMM (tf32 mma): x[N,128] @ W[128,64] + b -> g_xenc ----
// 128 thr / 4 warps; 32 rows per tile. warp = (mw = w&1: 16 rows, nw = w>>1: 32 cols)
#define XSE 132   // Xs stride (128-wide rows, +4 pad: bank = 4g+t)
#define WSE 72    // Ws stride (64-wide, +8 pad: bank = 8t+g)
__global__ void __launch_bounds__(128) encoder_kernel(
    const float* __restrict__ x, const float* __restrict__ W,
    const float* __restrict__ b) {
    __shared__ float    Xs[32 * XSE];
    __shared__ unsigned Ws[128 * WSE];
    __shared__ float    bs[64];
    int tid = threadIdx.x;
    int lane = tid & 31, w = tid >> 5;
    int g = lane >> 2, t = lane & 3;
    int mw = w & 1, nw = w >> 1;

    for (int i = tid; i < 128 * 64; i += 128)
        Ws[(i >> 6) * WSE + (i & 63)] = f2tf(W[i]);
    if (tid < 64) bs[tid] = b[tid];
    __syncthreads();

    for (int tile = blockIdx.x; tile < NTILES; tile += gridDim.x) {
        int r0 = tile * 32;
        __syncthreads();   // protect Xs reuse
        for (int i = tid; i < 32 * 32; i += 128) {   // 32 rows x 32 float4
            int r = i >> 5, c4 = i & 31;
            int row = r0 + r;
            float4 v = (row < NN) ? ((const float4*)(x + (size_t)row * FIN))[c4]
                                  : make_float4(0.f, 0.f, 0.f, 0.f);
            float* p = &Xs[r * XSE + 4 * c4];
            p[0] = __uint_as_float(f2tf(v.x));
            p[1] = __uint_as_float(f2tf(v.y));
            p[2] = __uint_as_float(f2tf(v.z));
            p[3] = __uint_as_float(f2tf(v.w));
        }
        __syncthreads();

        float acc[4][4];
#pragma unroll
        for (int i = 0; i < 4; i++)
#pragma unroll
            for (int j = 0; j < 4; j++) acc[i][j] = 0.f;

#pragma unroll
        for (int ks = 0; ks < 16; ks++) {
            int k0 = ks * 8;
            unsigned a0 = __float_as_uint(Xs[(mw * 16 + g) * XSE + k0 + t]);
            unsigned a1 = __float_as_uint(Xs[(mw * 16 + g + 8) * XSE + k0 + t]);
            unsigned a2 = __float_as_uint(Xs[(mw * 16 + g) * XSE + k0 + t + 4]);
            unsigned a3 = __float_as_uint(Xs[(mw * 16 + g + 8) * XSE + k0 + t + 4]);
#pragma unroll
            for (int nt = 0; nt < 4; nt++) {
                int n0 = nw * 32 + nt * 8;
                unsigned b0 = Ws[(k0 + t) * WSE + n0 + g];
                unsigned b1 = Ws[(k0 + t + 4) * WSE + n0 + g];
                mma8(acc[nt][0], acc[nt][1], acc[nt][2], acc[nt][3],
                     a0, a1, a2, a3, b0, b1);
            }
        }
#pragma unroll
        for (int nt = 0; nt < 4; nt++) {
            int col = nw * 32 + nt * 8 + 2 * t;
            int row = r0 + mw * 16 + g;
            if (row < NN) {
                float2 v = make_float2(acc[nt][0] + bs[col], acc[nt][1] + bs[col + 1]);
                *(float2*)&g_xenc[(size_t)row * HH + col] = v;
            }
            if (row + 8 < NN) {
                float2 v = make_float2(acc[nt][2] + bs[col], acc[nt][3] + bs[col + 1]);
                *(float2*)&g_xenc[(size_t)(row + 8) * HH + col] = v;
            }
        }
    }
}

// ---------------- softmax aggregation: warp per dst node ----------------
__global__ void agg_kernel(int sel, const float* __restrict__ tptr) {
    const float2* __restrict__ xin2 = (const float2*)(sel ? g_x1 : g_xenc);
    int gw = (blockIdx.x * blockDim.x + threadIdx.x) >> 5;
    int lane = threadIdx.x & 31;
    if (gw >= NN) return;
    float t = *tptr;
    int e0 = g_off[gw], e1 = g_off[gw + 1];

    float S0 = 0.f, S1 = 0.f, A0 = 0.f, A1 = 0.f;

    int e = e0;
    for (; e + 4 <= e1; e += 4) {
        int s0 = g_srcSorted[e];
        int s1 = g_srcSorted[e + 1];
        int s2 = g_srcSorted[e + 2];
        int s3 = g_srcSorted[e + 3];
        float2 v0 = xin2[s0 * 32 + lane];
        float2 v1 = xin2[s1 * 32 + lane];
        float2 v2 = xin2[s2 * 32 + lane];
        float2 v3 = xin2[s3 * 32 + lane];

        float m, ex;
        m = fmaxf(v0.x, 0.f) + MSG_EPS; ex = __expf(m * t); S0 += ex; A0 += m * ex;
        m = fmaxf(v0.y, 0.f) + MSG_EPS; ex = __expf(m * t); S1 += ex; A1 += m * ex;
        m = fmaxf(v1.x, 0.f) + MSG_EPS; ex = __expf(m * t); S0 += ex; A0 += m * ex;
        m = fmaxf(v1.y, 0.f) + MSG_EPS; ex = __expf(m * t); S1 += ex; A1 += m * ex;
        m = fmaxf(v2.x, 0.f) + MSG_EPS; ex = __expf(m * t); S0 += ex; A0 += m * ex;
        m = fmaxf(v2.y, 0.f) + MSG_EPS; ex = __expf(m * t); S1 += ex; A1 += m * ex;
        m = fmaxf(v3.x, 0.f) + MSG_EPS; ex = __expf(m * t); S0 += ex; A0 += m * ex;
        m = fmaxf(v3.y, 0.f) + MSG_EPS; ex = __expf(m * t); S1 += ex; A1 += m * ex;
    }
    for (; e < e1; e++) {
        int s = g_srcSorted[e];
        float2 v = xin2[s * 32 + lane];
        float m, ex;
        m = fmaxf(v.x, 0.f) + MSG_EPS; ex = __expf(m * t); S0 += ex; A0 += m * ex;
        m = fmaxf(v.y, 0.f) + MSG_EPS; ex = __expf(m * t); S1 += ex; A1 += m * ex;
    }
    float2 self = xin2[gw * 32 + lane];
    float2 o;
    o.x = A0 / (S0 + 1e-16f) + self.x;
    o.y = A1 / (S1 + 1e-16f) + self.y;
    ((float2*)g_tmp)[gw * 32 + lane] = o;
}

// ------------- fused MLP via tf32 mma (mlp1 and mlp2+final) -------------
// Per 32-row tile: GEMM1 (X[32,64]@W1[64,128]+b1) -> LN+relu -> GEMM2
// (@W2[128,64]+b2). final==0: store to g_x1. final==1: full epilogue -> out.
#define XSM 68    // Xs/Os stride (64-wide +4)
#define W1S 136   // W1s stride (128-wide +8)
#define W2S 72    // W2s stride (64-wide +8)
#define HSM 132   // Hs stride (128-wide +4)
__global__ void __launch_bounds__(128) mlp_kernel(
    int final_,
    const float* __restrict__ W1, const float* __restrict__ b1,
    const float* __restrict__ g1, const float* __restrict__ be1,
    const float* __restrict__ W2, const float* __restrict__ b2,
    const float* __restrict__ ln1g, const float* __restrict__ ln1b,
    const float* __restrict__ ng, const float* __restrict__ nb,
    const float* __restrict__ lw, const float* __restrict__ lb,
    float* __restrict__ out) {
    __shared__ float    Xs[32 * XSM];
    __shared__ unsigned W1s[64 * W1S];
    __shared__ unsigned W2s[128 * W2S];
    __shared__ float    Hs[32 * HSM];
    __shared__ float    Os[32 * XSM];
    __shared__ float    b1s[128];
    __shared__ float    b2s[64];

    int tid = threadIdx.x;
    int lane = tid & 31, w = tid >> 5;
    int g = lane >> 2, t = lane & 3;
    int mw = w & 1, nw = w >> 1;

    for (int i = tid; i < 64 * 128; i += 128)
        W1s[(i >> 7) * W1S + (i & 127)] = f2tf(W1[i]);
    for (int i = tid; i < 128 * 64; i += 128)
        W2s[(i >> 6) * W2S + (i & 63)] = f2tf(W2[i]);
    b1s[tid] = b1[tid];
    if (tid < 64) b2s[tid] = b2[tid];

    // per-lane LN params (channels 4*lane..4*lane+3 of the 128-wide hidden)
    float4 g1v = *(const float4*)(g1 + 4 * lane);
    float4 be1v = *(const float4*)(be1 + 4 * lane);
    // final-epilogue params (channels 2*lane, 2*lane+1)
    float2 l1g2, l1b2, ngx2, nbx2, ngh2, nbh2, lwx2, lwh2;
    float lbv = 0.f;
    if (final_) {
        l1g2 = *(const float2*)(ln1g + 2 * lane);
        l1b2 = *(const float2*)(ln1b + 2 * lane);
        ngx2 = *(const float2*)(ng + 2 * lane);
        nbx2 = *(const float2*)(nb + 2 * lane);
        ngh2 = *(const float2*)(ng + 64 + 2 * lane);
        nbh2 = *(const float2*)(nb + 64 + 2 * lane);
        lwx2 = *(const float2*)(lw + 2 * lane);
        lwh2 = *(const float2*)(lw + 64 + 2 * lane);
        lbv = lb[0];
    }
    __syncthreads();

    for (int tile = blockIdx.x; tile < NTILES; tile += gridDim.x) {
        int r0 = tile * 32;
        __syncthreads();   // protect Xs/Hs/Os reuse
        for (int i = tid; i < 32 * 16; i += 128) {   // 32 rows x 16 float4
            int r = i >> 4, c4 = i & 15;
            int row = r0 + r;
            float4 v = (row < NN) ? ((const float4*)(g_tmp + (size_t)row * HH))[c4]
                                  : make_float4(0.f, 0.f, 0.f, 0.f);
            float* p = &Xs[r * XSM + 4 * c4];
            p[0] = __uint_as_float(f2tf(v.x));
            p[1] = __uint_as_float(f2tf(v.y));
            p[2] = __uint_as_float(f2tf(v.z));
            p[3] = __uint_as_float(f2tf(v.w));
        }
        __syncthreads();

        // ---- GEMM1: warp covers rows mw*16..+16, cols nw*64..+64 ----
        {
            float acc[8][4];
#pragma unroll
            for (int i = 0; i < 8; i++)
#pragma unroll
                for (int j = 0; j < 4; j++) acc[i][j] = 0.f;
#pragma unroll
            for (int ks = 0; ks < 8; ks++) {
                int k0 = ks * 8;
                unsigned a0 = __float_as_uint(Xs[(mw * 16 + g) * XSM + k0 + t]);
                unsigned a1 = __float_as_uint(Xs[(mw * 16 + g + 8) * XSM + k0 + t]);
                unsigned a2 = __float_as_uint(Xs[(mw * 16 + g) * XSM + k0 + t + 4]);
                unsigned a3 = __float_as_uint(Xs[(mw * 16 + g + 8) * XSM + k0 + t + 4]);
#pragma unroll
                for (int nt = 0; nt < 8; nt++) {
                    int n0 = nw * 64 + nt * 8;
                    unsigned b0 = W1s[(k0 + t) * W1S + n0 + g];
                    unsigned b1f = W1s[(k0 + t + 4) * W1S + n0 + g];
                    mma8(acc[nt][0], acc[nt][1], acc[nt][2], acc[nt][3],
                         a0, a1, a2, a3, b0, b1f);
                }
            }
            // store H (+b1) to Hs
#pragma unroll
            for (int nt = 0; nt < 8; nt++) {
                int col = nw * 64 + nt * 8 + 2 * t;
                int r = mw * 16 + g;
                *(float2*)&Hs[r * HSM + col] =
                    make_float2(acc[nt][0] + b1s[col], acc[nt][1] + b1s[col + 1]);
                *(float2*)&Hs[(r + 8) * HSM + col] =
                    make_float2(acc[nt][2] + b1s[col], acc[nt][3] + b1s[col + 1]);
            }
        }
        __syncthreads();

        // ---- LN + relu per row (warp w: rows w*8..w*8+7), write tf32 ----
        for (int rr = w * 8; rr < w * 8 + 8; rr++) {
            float4 v = *(float4*)&Hs[rr * HSM + 4 * lane];
            float s = (v.x + v.y) + (v.z + v.w);
            float q = (v.x * v.x + v.y * v.y) + (v.z * v.z + v.w * v.w);
#pragma unroll
            for (int o = 16; o; o >>= 1) {
                s += __shfl_xor_sync(0xffffffffu, s, o);
                q += __shfl_xor_sync(0xffffffffu, q, o);
            }
            float mu = s * (1.f / HX);
            float rs = rsqrtf(q * (1.f / HX) - mu * mu + 1e-5f);
            float h0 = fmaxf((v.x - mu) * rs * g1v.x + be1v.x, 0.f);
            float h1 = fmaxf((v.y - mu) * rs * g1v.y + be1v.y, 0.f);
            float h2 = fmaxf((v.z - mu) * rs * g1v.z + be1v.z, 0.f);
            float h3 = fmaxf((v.w - mu) * rs * g1v.w + be1v.w, 0.f);
            float* p = &Hs[rr * HSM + 4 * lane];
            p[0] = __uint_as_float(f2tf(h0));
            p[1] = __uint_as_float(f2tf(h1));
            p[2] = __uint_as_float(f2tf(h2));
            p[3] = __uint_as_float(f2tf(h3));
        }
        __syncthreads();

        // ---- GEMM2: warp covers rows mw*16..+16, cols nw*32..+32 ----
        float acc2[4][4];
#pragma unroll
        for (int i = 0; i < 4; i++)
#pragma unroll
            for (int j = 0; j < 4; j++) acc2[i][j] = 0.f;
#pragma unroll
        for (int ks = 0; ks < 16; ks++) {
            int k0 = ks * 8;
            unsigned a0 = __float_as_uint(Hs[(mw * 16 + g) * HSM + k0 + t]);
            unsigned a1 = __float_as_uint(Hs[(mw * 16 + g + 8) * HSM + k0 + t]);
            unsigned a2 = __float_as_uint(Hs[(mw * 16 + g) * HSM + k0 + t + 4]);
            unsigned a3 = __float_as_uint(Hs[(mw * 16 + g + 8) * HSM + k0 + t + 4]);
#pragma unroll
            for (int nt = 0; nt < 4; nt++) {
                int n0 = nw * 32 + nt * 8;
                unsigned b0 = W2s[(k0 + t) * W2S + n0 + g];
                unsigned b1f = W2s[(k0 + t + 4) * W2S + n0 + g];
                mma8(acc2[nt][0], acc2[nt][1], acc2[nt][2], acc2[nt][3],
                     a0, a1, a2, a3, b0, b1f);
            }
        }

        if (!final_) {
            // store conv1 output to g_x1
#pragma unroll
            for (int nt = 0; nt < 4; nt++) {
                int col = nw * 32 + nt * 8 + 2 * t;
                int row = r0 + mw * 16 + g;
                if (row < NN) {
                    float2 v = make_float2(acc2[nt][0] + b2s[col], acc2[nt][1] + b2s[col + 1]);
                    *(float2*)&g_x1[(size_t)row * HH + col] = v;
                }
                if (row + 8 < NN) {
                    float2 v = make_float2(acc2[nt][2] + b2s[col], acc2[nt][3] + b2s[col + 1]);
                    *(float2*)&g_x1[(size_t)(row + 8) * HH + col] = v;
                }
            }
        } else {
            // stage h2 (+b2) into Os, then per-row network epilogue
#pragma unroll
            for (int nt = 0; nt < 4; nt++) {
                int col = nw * 32 + nt * 8 + 2 * t;
                int r = mw * 16 + g;
                *(float2*)&Os[r * XSM + col] =
                    make_float2(acc2[nt][0] + b2s[col], acc2[nt][1] + b2s[col + 1]);
                *(float2*)&Os[(r + 8) * XSM + col] =
                    make_float2(acc2[nt][2] + b2s[col], acc2[nt][3] + b2s[col + 1]);
            }
            __syncthreads();
            for (int rr = w * 8; rr < w * 8 + 8; rr++) {
                int row = r0 + rr;
                if (row >= NN) continue;
                float2 hv = *(float2*)&Os[rr * XSM + 2 * lane];
                float2 xv = *(const float2*)&g_x1[(size_t)row * HH + 2 * lane];

                // LN over 64 h-channels + relu
                float s = hv.x + hv.y;
                float q = hv.x * hv.x + hv.y * hv.y;
#pragma unroll
                for (int o = 16; o; o >>= 1) {
                    s += __shfl_xor_sync(0xffffffffu, s, o);
                    q += __shfl_xor_sync(0xffffffffu, q, o);
                }
                float muh = s * (1.f / 64.f);
                float rsh = rsqrtf(q * (1.f / 64.f) - muh * muh + 1e-5f);
                float hn0 = fmaxf((hv.x - muh) * rsh * l1g2.x + l1b2.x, 0.f);
                float hn1 = fmaxf((hv.y - muh) * rsh * l1g2.y + l1b2.y, 0.f);

                // LN over concat [x1(64), hn(64)] + relu + dot lin_W
                float s2 = xv.x + xv.y + hn0 + hn1;
                float q2 = xv.x * xv.x + xv.y * xv.y + hn0 * hn0 + hn1 * hn1;
#pragma unroll
                for (int o = 16; o; o >>= 1) {
                    s2 += __shfl_xor_sync(0xffffffffu, s2, o);
                    q2 += __shfl_xor_sync(0xffffffffu, q2, o);
                }
                float mu2 = s2 * (1.f / 128.f);
                float rs2 = rsqrtf(q2 * (1.f / 128.f) - mu2 * mu2 + 1e-5f);
                float d = fmaxf((xv.x - mu2) * rs2 * ngx2.x + nbx2.x, 0.f) * lwx2.x
                        + fmaxf((xv.y - mu2) * rs2 * ngx2.y + nbx2.y, 0.f) * lwx2.y
                        + fmaxf((hn0 - mu2) * rs2 * ngh2.x + nbh2.x, 0.f) * lwh2.x
                        + fmaxf((hn1 - mu2) * rs2 * ngh2.y + nbh2.y, 0.f) * lwh2.y;
#pragma unroll
                for (int o = 16; o; o >>= 1) d += __shfl_xor_sync(0xffffffffu, d, o);
                if (lane == 0) out[row] = d + lbv;
            }
        }
    }

    if (final_) {
        // re-zero counters / lookback state for the next run
        for (int i = blockIdx.x * blockDim.x + tid; i < NN; i += gridDim.x * blockDim.x)
            g_cnt[i] = 0;
        int i = blockIdx.x * blockDim.x + tid;
        if (i < SCAN_NBLK) *((unsigned long long*)&g_state[i]) = 0ULL;
    }
}

// ---------------- launch ----------------
extern "C" void kernel_launch(void* const* d_in, const int* in_sizes, int n_in,
                              void* d_out, int out_size) {
    const float* x    = (const float*)d_in[0];
    const void*  ei   = d_in[1];
    const float* encW = (const float*)d_in[2];
    const float* encB = (const float*)d_in[3];
    const float* t    = (const float*)d_in[4];
    const float* W1   = (const float*)d_in[5];
    const float* b1   = (const float*)d_in[6];
    const float* g1   = (const float*)d_in[7];
    const float* be1  = (const float*)d_in[8];
    const float* W2   = (const float*)d_in[9];
    const float* b2   = (const float*)d_in[10];
    const float* ln1g = (const float*)d_in[11];
    const float* ln1b = (const float*)d_in[12];
    const float* ng   = (const float*)d_in[13];
    const float* nb   = (const float*)d_in[14];
    const float* lw   = (const float*)d_in[15];
    const float* lb   = (const float*)d_in[16];
    float* out = (float*)d_out;

    const int AGG_BLOCKS = (NN * 32 + 255) / 256;

    count_kernel<<<EDGE_BLOCKS, 256>>>((const int*)ei);
    scan_lb_kernel<<<SCAN_NBLK, 256>>>();
    scatter_kernel<<<EDGE_BLOCKS, 256>>>((const int*)ei);
    encoder_kernel<<<592, 128>>>(x, encW, encB);
    agg_kernel<<<AGG_BLOCKS, 256>>>(0, t);
    mlp_kernel<<<296, 128>>>(0, W1, b1, g1, be1, W2, b2,
                             ln1g, ln1b, ng, nb, lw, lb, out);
    agg_kernel<<<AGG_BLOCKS, 256>>>(1, t);
    mlp_kernel<<<296, 128>>>(1, W1, b1, g1, be1, W2, b2,
                             ln1g, ln1b, ng, nb, lw, lb, out);
}

// round 9
// speedup vs baseline: 2.1115x; 1.0037x over previous
#include <cuda_runtime.h>

#define NN 50000
#define EE 800000
#define FIN 128
#define HH 64
#define HX 128   // 2H

#define MSG_EPS 1e-7f
#define SCAN_NBLK ((NN + 255) / 256)   // 196
#define NTILES ((NN + 31) / 32)        // 1563

// fused enc+count grid: every 6th block is an encoder block
#define FUSE_GRID 3750
#define ENC_STRIDE 625                 // number of encoder blocks

// ---------------- device scratch (no allocation allowed) ----------------
__device__ int   g_srcSorted[EE];
__device__ int   g_cnt[NN];            // 0 at run start (zeroed at run end)
__device__ int   g_off[NN + 1];
__device__ int   g_cursor[NN];
__device__ volatile unsigned long long g_state[SCAN_NBLK];
__device__ float g_xenc[NN * HH];
__device__ float g_tmp[NN * HH];
__device__ float g_x1[NN * HH];

// ---------------- tf32 mma helpers ----------------
__device__ __forceinline__ unsigned f2tf(float f) {
    unsigned r;
    asm("cvt.rna.tf32.f32 %0, %1;" : "=r"(r) : "f"(f));
    return r;
}
__device__ __forceinline__ void mma8(float& d0, float& d1, float& d2, float& d3,
                                     unsigned a0, unsigned a1, unsigned a2, unsigned a3,
                                     unsigned b0, unsigned b1) {
    asm("mma.sync.aligned.m16n8k8.row.col.f32.tf32.tf32.f32 "
        "{%0,%1,%2,%3},{%4,%5,%6,%7},{%8,%9},{%0,%1,%2,%3};"
        : "+f"(d0), "+f"(d1), "+f"(d2), "+f"(d3)
        : "r"(a0), "r"(a1), "r"(a2), "r"(a3), "r"(b0), "r"(b1));
}

// -------- inline dtype detect helper --------
__device__ __forceinline__ int detect_is64(const int* __restrict__ ei32,
                                           int t, int* s_flag) {
    int v = ei32[2 * (t & 127) + 1];
    int any = __syncthreads_or(v != 0);
    if (t == 0) *s_flag = !any;
    __syncthreads();
    return *s_flag;
}
__device__ __forceinline__ void decode_edge(const int* __restrict__ ei32,
                                            int is64, int e, int* s, int* d) {
    if (is64) {
        const long long* p = (const long long*)ei32;
        *s = (int)p[e];
        *d = (int)p[EE + e];
    } else {
        *s = ei32[e];
        *d = ei32[EE + e];
    }
}

// ------- fused encoder GEMM (tf32 mma) + degree count ----------
// blocks with blockIdx.x % 6 == 0 -> encoder role (grid-stride over 32-row tiles)
// all other blocks -> count role (256 edges per block, 2 per thread)
#define XSE 132   // Xs stride (128-wide rows, +4 pad)
#define WSE 72    // Ws stride (64-wide, +8 pad)
__global__ void __launch_bounds__(128) enc_count_kernel(
    const float* __restrict__ x, const float* __restrict__ W,
    const float* __restrict__ b, const int* __restrict__ ei32) {
    __shared__ float    Xs[32 * XSE];
    __shared__ unsigned Ws[128 * WSE];
    __shared__ float    bs[64];
    int tid = threadIdx.x;
    int bi = blockIdx.x;

    if (bi % 6 != 0) {
        // ---- count role ----
        __shared__ int s_is64;
        int is64 = detect_is64(ei32, tid, &s_is64);
        int cntRank = bi - (bi / 6 + 1);           // 0..3124
        int e0 = cntRank * 256 + tid;
#pragma unroll
        for (int rep = 0; rep < 2; rep++) {
            int e = e0 + rep * 128;
            if (e < EE) {
                int s, d;
                decode_edge(ei32, is64, e, &s, &d);
                atomicAdd(&g_cnt[d], 1);
            }
        }
        return;
    }

    // ---- encoder role ----
    int encRank = bi / 6;                          // 0..624
    int lane = tid & 31, w = tid >> 5;
    int g = lane >> 2, t = lane & 3;
    int mw = w & 1, nw = w >> 1;

    for (int i = tid; i < 128 * 64; i += 128)
        Ws[(i >> 6) * WSE + (i & 63)] = f2tf(W[i]);
    if (tid < 64) bs[tid] = b[tid];
    __syncthreads();

    for (int tile = encRank; tile < NTILES; tile += ENC_STRIDE) {
        int r0 = tile * 32;
        __syncthreads();   // protect Xs reuse
        for (int i = tid; i < 32 * 32; i += 128) {   // 32 rows x 32 float4
            int r = i >> 5, c4 = i & 31;
            int row = r0 + r;
            float4 v = (row < NN) ? ((const float4*)(x + (size_t)row * FIN))[c4]
                                  : make_float4(0.f, 0.f, 0.f, 0.f);
            float* p = &Xs[r * XSE + 4 * c4];
            p[0] = __uint_as_float(f2tf(v.x));
            p[1] = __uint_as_float(f2tf(v.y));
            p[2] = __uint_as_float(f2tf(v.z));
            p[3] = __uint_as_float(f2tf(v.w));
        }
        __syncthreads();

        float acc[4][4];
#pragma unroll
        for (int i = 0; i < 4; i++)
#pragma unroll
            for (int j = 0; j < 4; j++) acc[i][j] = 0.f;

#pragma unroll
        for (int ks = 0; ks < 16; ks++) {
            int k0 = ks * 8;
            unsigned a0 = __float_as_uint(Xs[(mw * 16 + g) * XSE + k0 + t]);
            unsigned a1 = __float_as_uint(Xs[(mw * 16 + g + 8) * XSE + k0 + t]);
            unsigned a2 = __float_as_uint(Xs[(mw * 16 + g) * XSE + k0 + t + 4]);
            unsigned a3 = __float_as_uint(Xs[(mw * 16 + g + 8) * XSE + k0 + t + 4]);
#pragma unroll
            for (int nt = 0; nt < 4; nt++) {
                int n0 = nw * 32 + nt * 8;
                unsigned b0 = Ws[(k0 + t) * WSE + n0 + g];
                unsigned b1 = Ws[(k0 + t + 4) * WSE + n0 + g];
                mma8(acc[nt][0], acc[nt][1], acc[nt][2], acc[nt][3],
                     a0, a1, a2, a3, b0, b1);
            }
        }
#pragma unroll
        for (int nt = 0; nt < 4; nt++) {
            int col = nw * 32 + nt * 8 + 2 * t;
            int row = r0 + mw * 16 + g;
            if (row < NN) {
                float2 v = make_float2(acc[nt][0] + bs[col], acc[nt][1] + bs[col + 1]);
                *(float2*)&g_xenc[(size_t)row * HH + col] = v;
            }
            if (row + 8 < NN) {
                float2 v = make_float2(acc[nt][2] + bs[col], acc[nt][3] + bs[col + 1]);
                *(float2*)&g_xenc[(size_t)(row + 8) * HH + col] = v;
            }
        }
    }
}

// ---- block exclusive scan helper ----
__device__ __forceinline__ int block_excl_scan_256(int v, int* wsum, int t) {
    int lane = t & 31;
    int w = t >> 5;
    int incl = v;
#pragma unroll
    for (int o = 1; o < 32; o <<= 1) {
        int n = __shfl_up_sync(0xffffffffu, incl, o);
        if (lane >= o) incl += n;
    }
    if (lane == 31) wsum[w] = incl;
    __syncthreads();
    if (t == 0) {
        int run = 0;
#pragma unroll
        for (int i = 0; i < 8; i++) { int c = wsum[i]; wsum[i] = run; run += c; }
        wsum[8] = run;
    }
    __syncthreads();
    return incl - v + wsum[w];
}

// ---- single-pass decoupled-lookback scan ----
__global__ void scan_lb_kernel() {
    __shared__ int wsum[9];
    __shared__ int s_excl;
    int b = blockIdx.x, t = threadIdx.x;
    int idx = b * 256 + t;
    int v = (idx < NN) ? g_cnt[idx] : 0;
    int excl = block_excl_scan_256(v, wsum, t);
    int total = wsum[8];

    if (t == 0) {
        unsigned long long st = (b == 0)
            ? ((2ULL << 32) | (unsigned)total)
            : ((1ULL << 32) | (unsigned)total);
        atomicExch((unsigned long long*)&g_state[b], st);
        if (b == 0) s_excl = 0;
    }
    if (b > 0 && t < 32) {
        int lane = t;
        int look = b - 1;
        int run = 0;
        while (true) {
            int ip = look - lane;
            unsigned long long s;
            if (ip >= 0) {
                do { s = g_state[ip]; } while ((s >> 32) == 0);
            } else {
                s = (2ULL << 32);
            }
            int isPref = ((s >> 32) == 2u);
            unsigned mask = __ballot_sync(0xffffffffu, isPref);
            int val = (int)(s & 0xffffffffu);
            if (mask) {
                int p = __ffs(mask) - 1;
                int contrib = (lane <= p) ? val : 0;
#pragma unroll
                for (int o = 16; o; o >>= 1) contrib += __shfl_xor_sync(0xffffffffu, contrib, o);
                run += contrib;
                break;
            } else {
                int contrib = val;
#pragma unroll
                for (int o = 16; o; o >>= 1) contrib += __shfl_xor_sync(0xffffffffu, contrib, o);
                run += contrib;
                look -= 32;
            }
        }
        if (lane == 0) {
            s_excl = run;
            atomicExch((unsigned long long*)&g_state[b],
                       (2ULL << 32) | (unsigned)(run + total));
        }
    }
    __syncthreads();
    int base = s_excl;
    if (idx < NN) { int off = excl + base; g_off[idx] = off; g_cursor[idx] = off; }
    if (b == SCAN_NBLK - 1 && t == 0) g_off[NN] = EE;
}

// ---------------- scatter edges into CSR order ----------------
__global__ void scatter_kernel(const int* __restrict__ ei32) {
    __shared__ int s_is64;
    int t = threadIdx.x;
    int is64 = detect_is64(ei32, t, &s_is64);
    int e = blockIdx.x * blockDim.x + t;
    if (e >= EE) return;
    int s, d;
    decode_edge(ei32, is64, e, &s, &d);
    int pos = atomicAdd(&g_cursor[d], 1);
    g_srcSorted[pos] = s;
}

// ---------------- softmax aggregation: warp per dst node ----------------
__global__ void agg_kernel(int sel, const float* __restrict__ tptr) {
    const float2* __restrict__ xin2 = (const float2*)(sel ? g_x1 : g_xenc);
    int gw = (blockIdx.x * blockDim.x + threadIdx.x) >> 5;
    int lane = threadIdx.x & 31;
    if (gw >= NN) return;
    float t = *tptr;
    int e0 = g_off[gw], e1 = g_off[gw + 1];

    float S0 = 0.f, S1 = 0.f, A0 = 0.f, A1 = 0.f;

    int e = e0;
    for (; e + 4 <= e1; e += 4) {
        int s0 = g_srcSorted[e];
        int s1 = g_srcSorted[e + 1];
        int s2 = g_srcSorted[e + 2];
        int s3 = g_srcSorted[e + 3];
        float2 v0 = xin2[s0 * 32 + lane];
        float2 v1 = xin2[s1 * 32 + lane];
        float2 v2 = xin2[s2 * 32 + lane];
        float2 v3 = xin2[s3 * 32 + lane];

        float m, ex;
        m = fmaxf(v0.x, 0.f) + MSG_EPS; ex = __expf(m * t); S0 += ex; A0 += m * ex;
        m = fmaxf(v0.y, 0.f) + MSG_EPS; ex = __expf(m * t); S1 += ex; A1 += m * ex;
        m = fmaxf(v1.x, 0.f) + MSG_EPS; ex = __expf(m * t); S0 += ex; A0 += m * ex;
        m = fmaxf(v1.y, 0.f) + MSG_EPS; ex = __expf(m * t); S1 += ex; A1 += m * ex;
        m = fmaxf(v2.x, 0.f) + MSG_EPS; ex = __expf(m * t); S0 += ex; A0 += m * ex;
        m = fmaxf(v2.y, 0.f) + MSG_EPS; ex = __expf(m * t); S1 += ex; A1 += m * ex;
        m = fmaxf(v3.x, 0.f) + MSG_EPS; ex = __expf(m * t); S0 += ex; A0 += m * ex;
        m = fmaxf(v3.y, 0.f) + MSG_EPS; ex = __expf(m * t); S1 += ex; A1 += m * ex;
    }
    for (; e < e1; e++) {
        int s = g_srcSorted[e];
        float2 v = xin2[s * 32 + lane];
        float m, ex;
        m = fmaxf(v.x, 0.f) + MSG_EPS; ex = __expf(m * t); S0 += ex; A0 += m * ex;
        m = fmaxf(v.y, 0.f) + MSG_EPS; ex = __expf(m * t); S1 += ex; A1 += m * ex;
    }
    float2 self = xin2[gw * 32 + lane];
    float2 o;
    o.x = A0 / (S0 + 1e-16f) + self.x;
    o.y = A1 / (S1 + 1e-16f) + self.y;
    ((float2*)g_tmp)[gw * 32 + lane] = o;
}

// ------------- fused MLP via tf32 mma (mlp1 and mlp2+final) -------------
#define XSM 68    // Xs/Os stride (64-wide +4)
#define W1S 136   // W1s stride (128-wide +8)
#define W2S 72    // W2s stride (64-wide +8)
#define HSM 132   // Hs stride (128-wide +4)
__global__ void __launch_bounds__(128) mlp_kernel(
    int final_,
    const float* __restrict__ W1, const float* __restrict__ b1,
    const float* __restrict__ g1, const float* __restrict__ be1,
    const float* __restrict__ W2, const float* __restrict__ b2,
    const float* __restrict__ ln1g, const float* __restrict__ ln1b,
    const float* __restrict__ ng, const float* __restrict__ nb,
    const float* __restrict__ lw, const float* __restrict__ lb,
    float* __restrict__ out) {
    __shared__ float    Xs[32 * XSM];
    __shared__ unsigned W1s[64 * W1S];
    __shared__ unsigned W2s[128 * W2S];
    __shared__ float    Hs[32 * HSM];
    __shared__ float    Os[32 * XSM];
    __shared__ float    b1s[128];
    __shared__ float    b2s[64];

    int tid = threadIdx.x;
    int lane = tid & 31, w = tid >> 5;
    int g = lane >> 2, t = lane & 3;
    int mw = w & 1, nw = w >> 1;

    for (int i = tid; i < 64 * 128; i += 128)
        W1s[(i >> 7) * W1S + (i & 127)] = f2tf(W1[i]);
    for (int i = tid; i < 128 * 64; i += 128)
        W2s[(i >> 6) * W2S + (i & 63)] = f2tf(W2[i]);
    b1s[tid] = b1[tid];
    if (tid < 64) b2s[tid] = b2[tid];

    float4 g1v = *(const float4*)(g1 + 4 * lane);
    float4 be1v = *(const float4*)(be1 + 4 * lane);
    float2 l1g2, l1b2, ngx2, nbx2, ngh2, nbh2, lwx2, lwh2;
    float lbv = 0.f;
    if (final_) {
        l1g2 = *(const float2*)(ln1g + 2 * lane);
        l1b2 = *(const float2*)(ln1b + 2 * lane);
        ngx2 = *(const float2*)(ng + 2 * lane);
        nbx2 = *(const float2*)(nb + 2 * lane);
        ngh2 = *(const float2*)(ng + 64 + 2 * lane);
        nbh2 = *(const float2*)(nb + 64 + 2 * lane);
        lwx2 = *(const float2*)(lw + 2 * lane);
        lwh2 = *(const float2*)(lw + 64 + 2 * lane);
        lbv = lb[0];
    }
    __syncthreads();

    for (int tile = blockIdx.x; tile < NTILES; tile += gridDim.x) {
        int r0 = tile * 32;
        __syncthreads();
        for (int i = tid; i < 32 * 16; i += 128) {
            int r = i >> 4, c4 = i & 15;
            int row = r0 + r;
            float4 v = (row < NN) ? ((const float4*)(g_tmp + (size_t)row * HH))[c4]
                                  : make_float4(0.f, 0.f, 0.f, 0.f);
            float* p = &Xs[r * XSM + 4 * c4];
            p[0] = __uint_as_float(f2tf(v.x));
            p[1] = __uint_as_float(f2tf(v.y));
            p[2] = __uint_as_float(f2tf(v.z));
            p[3] = __uint_as_float(f2tf(v.w));
        }
        __syncthreads();

        // ---- GEMM1 ----
        {
            float acc[8][4];
#pragma unroll
            for (int i = 0; i < 8; i++)
#pragma unroll
                for (int j = 0; j < 4; j++) acc[i][j] = 0.f;
#pragma unroll
            for (int ks = 0; ks < 8; ks++) {
                int k0 = ks * 8;
                unsigned a0 = __float_as_uint(Xs[(mw * 16 + g) * XSM + k0 + t]);
                unsigned a1 = __float_as_uint(Xs[(mw * 16 + g + 8) * XSM + k0 + t]);
                unsigned a2 = __float_as_uint(Xs[(mw * 16 + g) * XSM + k0 + t + 4]);
                unsigned a3 = __float_as_uint(Xs[(mw * 16 + g + 8) * XSM + k0 + t + 4]);
#pragma unroll
                for (int nt = 0; nt < 8; nt++) {
                    int n0 = nw * 64 + nt * 8;
                    unsigned b0 = W1s[(k0 + t) * W1S + n0 + g];
                    unsigned b1f = W1s[(k0 + t + 4) * W1S + n0 + g];
                    mma8(acc[nt][0], acc[nt][1], acc[nt][2], acc[nt][3],
                         a0, a1, a2, a3, b0, b1f);
                }
            }
#pragma unroll
            for (int nt = 0; nt < 8; nt++) {
                int col = nw * 64 + nt * 8 + 2 * t;
                int r = mw * 16 + g;
                *(float2*)&Hs[r * HSM + col] =
                    make_float2(acc[nt][0] + b1s[col], acc[nt][1] + b1s[col + 1]);
                *(float2*)&Hs[(r + 8) * HSM + col] =
                    make_float2(acc[nt][2] + b1s[col], acc[nt][3] + b1s[col + 1]);
            }
        }
        __syncthreads();

        // ---- LN + relu per row ----
        for (int rr = w * 8; rr < w * 8 + 8; rr++) {
            float4 v = *(float4*)&Hs[rr * HSM + 4 * lane];
            float s = (v.x + v.y) + (v.z + v.w);
            float q = (v.x * v.x + v.y * v.y) + (v.z * v.z + v.w * v.w);
#pragma unroll
            for (int o = 16; o; o >>= 1) {
                s += __shfl_xor_sync(0xffffffffu, s, o);
                q += __shfl_xor_sync(0xffffffffu, q, o);
            }
            float mu = s * (1.f / HX);
            float rs = rsqrtf(q * (1.f / HX) - mu * mu + 1e-5f);
            float h0 = fmaxf((v.x - mu) * rs * g1v.x + be1v.x, 0.f);
            float h1 = fmaxf((v.y - mu) * rs * g1v.y + be1v.y, 0.f);
            float h2 = fmaxf((v.z - mu) * rs * g1v.z + be1v.z, 0.f);
            float h3 = fmaxf((v.w - mu) * rs * g1v.w + be1v.w, 0.f);
            float* p = &Hs[rr * HSM + 4 * lane];
            p[0] = __uint_as_float(f2tf(h0));
            p[1] = __uint_as_float(f2tf(h1));
            p[2] = __uint_as_float(f2tf(h2));
            p[3] = __uint_as_float(f2tf(h3));
        }
        __syncthreads();

        // ---- GEMM2 ----
        float acc2[4][4];
#pragma unroll
        for (int i = 0; i < 4; i++)
#pragma unroll
            for (int j = 0; j < 4; j++) acc2[i][j] = 0.f;
#pragma unroll
        for (int ks = 0; ks < 16; ks++) {
            int k0 = ks * 8;
            unsigned a0 = __float_as_uint(Hs[(mw * 16 + g) * HSM + k0 + t]);
            unsigned a1 = __float_as_uint(Hs[(mw * 16 + g + 8) * HSM + k0 + t]);
            unsigned a2 = __float_as_uint(Hs[(mw * 16 + g) * HSM + k0 + t + 4]);
            unsigned a3 = __float_as_uint(Hs[(mw * 16 + g + 8) * HSM + k0 + t + 4]);
#pragma unroll
            for (int nt = 0; nt < 4; nt++) {
                int n0 = nw * 32 + nt * 8;
                unsigned b0 = W2s[(k0 + t) * W2S + n0 + g];
                unsigned b1f = W2s[(k0 + t + 4) * W2S + n0 + g];
                mma8(acc2[nt][0], acc2[nt][1], acc2[nt][2], acc2[nt][3],
                     a0, a1, a2, a3, b0, b1f);
            }
        }

        if (!final_) {
#pragma unroll
            for (int nt = 0; nt < 4; nt++) {
                int col = nw * 32 + nt * 8 + 2 * t;
                int row = r0 + mw * 16 + g;
                if (row < NN) {
                    float2 v = make_float2(acc2[nt][0] + b2s[col], acc2[nt][1] + b2s[col + 1]);
                    *(float2*)&g_x1[(size_t)row * HH + col] = v;
                }
                if (row + 8 < NN) {
                    float2 v = make_float2(acc2[nt][2] + b2s[col], acc2[nt][3] + b2s[col + 1]);
                    *(float2*)&g_x1[(size_t)(row + 8) * HH + col] = v;
                }
            }
        } else {
#pragma unroll
            for (int nt = 0; nt < 4; nt++) {
                int col = nw * 32 + nt * 8 + 2 * t;
                int r = mw * 16 + g;
                *(float2*)&Os[r * XSM + col] =
                    make_float2(acc2[nt][0] + b2s[col], acc2[nt][1] + b2s[col + 1]);
                *(float2*)&Os[(r + 8) * XSM + col] =
                    make_float2(acc2[nt][2] + b2s[col], acc2[nt][3] + b2s[col + 1]);
            }
            __syncthreads();
            for (int rr = w * 8; rr < w * 8 + 8; rr++) {
                int row = r0 + rr;
                if (row >= NN) continue;
                float2 hv = *(float2*)&Os[rr * XSM + 2 * lane];
                float2 xv = *(const float2*)&g_x1[(size_t)row * HH + 2 * lane];

                float s = hv.x + hv.y;
                float q = hv.x * hv.x + hv.y * hv.y;
#pragma unroll
                for (int o = 16; o; o >>= 1) {
                    s += __shfl_xor_sync(0xffffffffu, s, o);
                    q += __shfl_xor_sync(0xffffffffu, q, o);
                }
                float muh = s * (1.f / 64.f);
                float rsh = rsqrtf(q * (1.f / 64.f) - muh * muh + 1e-5f);
                float hn0 = fmaxf((hv.x - muh) * rsh * l1g2.x + l1b2.x, 0.f);
                float hn1 = fmaxf((hv.y - muh) * rsh * l1g2.y + l1b2.y, 0.f);

                float s2 = xv.x + xv.y + hn0 + hn1;
                float q2 = xv.x * xv.x + xv.y * xv.y + hn0 * hn0 + hn1 * hn1;
#pragma unroll
                for (int o = 16; o; o >>= 1) {
                    s2 += __shfl_xor_sync(0xffffffffu, s2, o);
                    q2 += __shfl_xor_sync(0xffffffffu, q2, o);
                }
                float mu2 = s2 * (1.f / 128.f);
                float rs2 = rsqrtf(q2 * (1.f / 128.f) - mu2 * mu2 + 1e-5f);
                float d = fmaxf((xv.x - mu2) * rs2 * ngx2.x + nbx2.x, 0.f) * lwx2.x
                        + fmaxf((xv.y - mu2) * rs2 * ngx2.y + nbx2.y, 0.f) * lwx2.y
                        + fmaxf((hn0 - mu2) * rs2 * ngh2.x + nbh2.x, 0.f) * lwh2.x
                        + fmaxf((hn1 - mu2) * rs2 * ngh2.y + nbh2.y, 0.f) * lwh2.y;
#pragma unroll
                for (int o = 16; o; o >>= 1) d += __shfl_xor_sync(0xffffffffu, d, o);
                if (lane == 0) out[row] = d + lbv;
            }
        }
    }

    if (final_) {
        for (int i = blockIdx.x * blockDim.x + tid; i < NN; i += gridDim.x * blockDim.x)
            g_cnt[i] = 0;
        int i = blockIdx.x * blockDim.x + tid;
        if (i < SCAN_NBLK) *((unsigned long long*)&g_state[i]) = 0ULL;
    }
}

// ---------------- launch ----------------
extern "C" void kernel_launch(void* const* d_in, const int* in_sizes, int n_in,
                              void* d_out, int out_size) {
    const float* x    = (const float*)d_in[0];
    const void*  ei   = d_in[1];
    const float* encW = (const float*)d_in[2];
    const float* encB = (const float*)d_in[3];
    const float* t    = (const float*)d_in[4];
    const float* W1   = (const float*)d_in[5];
    const float* b1   = (const float*)d_in[6];
    const float* g1   = (const float*)d_in[7];
    const float* be1  = (const float*)d_in[8];
    const float* W2   = (const float*)d_in[9];
    const float* b2   = (const float*)d_in[10];
    const float* ln1g = (const float*)d_in[11];
    const float* ln1b = (const float*)d_in[12];
    const float* ng   = (const float*)d_in[13];
    const float* nb   = (const float*)d_in[14];
    const float* lw   = (const float*)d_in[15];
    const float* lb   = (const float*)d_in[16];
    float* out = (float*)d_out;

    const int AGG_BLOCKS = (NN * 32 + 255) / 256;

    enc_count_kernel<<<FUSE_GRID, 128>>>(x, encW, encB, (const int*)ei);
    scan_lb_kernel<<<SCAN_NBLK, 256>>>();
    scatter_kernel<<<(EE + 255) / 256, 256>>>((const int*)ei);
    agg_kernel<<<AGG_BLOCKS, 256>>>(0, t);               // 4th launch -> ncu
    mlp_kernel<<<296, 128>>>(0, W1, b1, g1, be1, W2, b2,
                             ln1g, ln1b, ng, nb, lw, lb, out);
    agg_kernel<<<AGG_BLOCKS, 256>>>(1, t);
    mlp_kernel<<<296, 128>>>(1, W1, b1, g1, be1, W2, b2,
                             ln1g, ln1b, ng, nb, lw, lb, out);
}

// round 10
// speedup vs baseline: 2.2311x; 1.0566x over previous
#include <cuda_runtime.h>

#define NN 50000
#define EE 800000
#define FIN 128
#define HH 64
#define HX 128   // 2H

#define MSG_EPS 1e-7f
#define SCAN_NBLK ((NN + 255) / 256)   // 196
#define NTILES ((NN + 31) / 32)        // 1563

// fused enc+count grid: every 6th block is an encoder block
#define FUSE_GRID 3750
#define ENC_STRIDE 625                 // number of encoder blocks

// ---------------- device scratch (no allocation allowed) ----------------
__device__ int   g_srcSorted[EE];
__device__ int   g_cnt[NN];            // 0 at run start (zeroed at run end)
__device__ int   g_off[NN + 1];
__device__ int   g_cursor[NN];
__device__ volatile unsigned long long g_state[SCAN_NBLK];
__device__ float g_xenc[NN * HH];
__device__ float g_tmp[NN * HH];
__device__ float g_x1[NN * HH];

// ---------------- tf32 mma helpers ----------------
__device__ __forceinline__ unsigned f2tf(float f) {
    unsigned r;
    asm("cvt.rna.tf32.f32 %0, %1;" : "=r"(r) : "f"(f));
    return r;
}
__device__ __forceinline__ float ex2f(float x) {
    float r;
    asm("ex2.approx.ftz.f32 %0, %1;" : "=f"(r) : "f"(x));
    return r;
}
__device__ __forceinline__ void mma8(float& d0, float& d1, float& d2, float& d3,
                                     unsigned a0, unsigned a1, unsigned a2, unsigned a3,
                                     unsigned b0, unsigned b1) {
    asm("mma.sync.aligned.m16n8k8.row.col.f32.tf32.tf32.f32 "
        "{%0,%1,%2,%3},{%4,%5,%6,%7},{%8,%9},{%0,%1,%2,%3};"
        : "+f"(d0), "+f"(d1), "+f"(d2), "+f"(d3)
        : "r"(a0), "r"(a1), "r"(a2), "r"(a3), "r"(b0), "r"(b1));
}

// -------- inline dtype detect helper --------
__device__ __forceinline__ int detect_is64(const int* __restrict__ ei32,
                                           int t, int* s_flag) {
    int v = ei32[2 * (t & 127) + 1];
    int any = __syncthreads_or(v != 0);
    if (t == 0) *s_flag = !any;
    __syncthreads();
    return *s_flag;
}
__device__ __forceinline__ void decode_edge(const int* __restrict__ ei32,
                                            int is64, int e, int* s, int* d) {
    if (is64) {
        const long long* p = (const long long*)ei32;
        *s = (int)p[e];
        *d = (int)p[EE + e];
    } else {
        *s = ei32[e];
        *d = ei32[EE + e];
    }
}

// ------- fused encoder GEMM (tf32 mma) + degree count ----------
#define XSE 132   // Xs stride (128-wide rows, +4 pad)
#define WSE 72    // Ws stride (64-wide, +8 pad)
__global__ void __launch_bounds__(128) enc_count_kernel(
    const float* __restrict__ x, const float* __restrict__ W,
    const float* __restrict__ b, const int* __restrict__ ei32) {
    __shared__ float    Xs[32 * XSE];
    __shared__ unsigned Ws[128 * WSE];
    __shared__ float    bs[64];
    int tid = threadIdx.x;
    int bi = blockIdx.x;

    if (bi % 6 != 0) {
        // ---- count role ----
        __shared__ int s_is64;
        int is64 = detect_is64(ei32, tid, &s_is64);
        int cntRank = bi - (bi / 6 + 1);           // 0..3124
        int e0 = cntRank * 256 + tid;
#pragma unroll
        for (int rep = 0; rep < 2; rep++) {
            int e = e0 + rep * 128;
            if (e < EE) {
                int s, d;
                decode_edge(ei32, is64, e, &s, &d);
                atomicAdd(&g_cnt[d], 1);
            }
        }
        return;
    }

    // ---- encoder role ----
    int encRank = bi / 6;                          // 0..624
    int lane = tid & 31, w = tid >> 5;
    int g = lane >> 2, t = lane & 3;
    int mw = w & 1, nw = w >> 1;

    for (int i = tid; i < 128 * 64; i += 128)
        Ws[(i >> 6) * WSE + (i & 63)] = f2tf(W[i]);
    if (tid < 64) bs[tid] = b[tid];
    __syncthreads();

    for (int tile = encRank; tile < NTILES; tile += ENC_STRIDE) {
        int r0 = tile * 32;
        __syncthreads();   // protect Xs reuse
        for (int i = tid; i < 32 * 32; i += 128) {   // 32 rows x 32 float4
            int r = i >> 5, c4 = i & 31;
            int row = r0 + r;
            float4 v = (row < NN) ? ((const float4*)(x + (size_t)row * FIN))[c4]
                                  : make_float4(0.f, 0.f, 0.f, 0.f);
            float* p = &Xs[r * XSE + 4 * c4];
            p[0] = __uint_as_float(f2tf(v.x));
            p[1] = __uint_as_float(f2tf(v.y));
            p[2] = __uint_as_float(f2tf(v.z));
            p[3] = __uint_as_float(f2tf(v.w));
        }
        __syncthreads();

        float acc[4][4];
#pragma unroll
        for (int i = 0; i < 4; i++)
#pragma unroll
            for (int j = 0; j < 4; j++) acc[i][j] = 0.f;

#pragma unroll
        for (int ks = 0; ks < 16; ks++) {
            int k0 = ks * 8;
            unsigned a0 = __float_as_uint(Xs[(mw * 16 + g) * XSE + k0 + t]);
            unsigned a1 = __float_as_uint(Xs[(mw * 16 + g + 8) * XSE + k0 + t]);
            unsigned a2 = __float_as_uint(Xs[(mw * 16 + g) * XSE + k0 + t + 4]);
            unsigned a3 = __float_as_uint(Xs[(mw * 16 + g + 8) * XSE + k0 + t + 4]);
#pragma unroll
            for (int nt = 0; nt < 4; nt++) {
                int n0 = nw * 32 + nt * 8;
                unsigned b0 = Ws[(k0 + t) * WSE + n0 + g];
                unsigned b1 = Ws[(k0 + t + 4) * WSE + n0 + g];
                mma8(acc[nt][0], acc[nt][1], acc[nt][2], acc[nt][3],
                     a0, a1, a2, a3, b0, b1);
            }
        }
#pragma unroll
        for (int nt = 0; nt < 4; nt++) {
            int col = nw * 32 + nt * 8 + 2 * t;
            int row = r0 + mw * 16 + g;
            if (row < NN) {
                float2 v = make_float2(acc[nt][0] + bs[col], acc[nt][1] + bs[col + 1]);
                *(float2*)&g_xenc[(size_t)row * HH + col] = v;
            }
            if (row + 8 < NN) {
                float2 v = make_float2(acc[nt][2] + bs[col], acc[nt][3] + bs[col + 1]);
                *(float2*)&g_xenc[(size_t)(row + 8) * HH + col] = v;
            }
        }
    }
}

// ---- block exclusive scan helper ----
__device__ __forceinline__ int block_excl_scan_256(int v, int* wsum, int t) {
    int lane = t & 31;
    int w = t >> 5;
    int incl = v;
#pragma unroll
    for (int o = 1; o < 32; o <<= 1) {
        int n = __shfl_up_sync(0xffffffffu, incl, o);
        if (lane >= o) incl += n;
    }
    if (lane == 31) wsum[w] = incl;
    __syncthreads();
    if (t == 0) {
        int run = 0;
#pragma unroll
        for (int i = 0; i < 8; i++) { int c = wsum[i]; wsum[i] = run; run += c; }
        wsum[8] = run;
    }
    __syncthreads();
    return incl - v + wsum[w];
}

// ---- single-pass decoupled-lookback scan ----
__global__ void scan_lb_kernel() {
    __shared__ int wsum[9];
    __shared__ int s_excl;
    int b = blockIdx.x, t = threadIdx.x;
    int idx = b * 256 + t;
    int v = (idx < NN) ? g_cnt[idx] : 0;
    int excl = block_excl_scan_256(v, wsum, t);
    int total = wsum[8];

    if (t == 0) {
        unsigned long long st = (b == 0)
            ? ((2ULL << 32) | (unsigned)total)
            : ((1ULL << 32) | (unsigned)total);
        atomicExch((unsigned long long*)&g_state[b], st);
        if (b == 0) s_excl = 0;
    }
    if (b > 0 && t < 32) {
        int lane = t;
        int look = b - 1;
        int run = 0;
        while (true) {
            int ip = look - lane;
            unsigned long long s;
            if (ip >= 0) {
                do { s = g_state[ip]; } while ((s >> 32) == 0);
            } else {
                s = (2ULL << 32);
            }
            int isPref = ((s >> 32) == 2u);
            unsigned mask = __ballot_sync(0xffffffffu, isPref);
            int val = (int)(s & 0xffffffffu);
            if (mask) {
                int p = __ffs(mask) - 1;
                int contrib = (lane <= p) ? val : 0;
#pragma unroll
                for (int o = 16; o; o >>= 1) contrib += __shfl_xor_sync(0xffffffffu, contrib, o);
                run += contrib;
                break;
            } else {
                int contrib = val;
#pragma unroll
                for (int o = 16; o; o >>= 1) contrib += __shfl_xor_sync(0xffffffffu, contrib, o);
                run += contrib;
                look -= 32;
            }
        }
        if (lane == 0) {
            s_excl = run;
            atomicExch((unsigned long long*)&g_state[b],
                       (2ULL << 32) | (unsigned)(run + total));
        }
    }
    __syncthreads();
    int base = s_excl;
    if (idx < NN) { int off = excl + base; g_off[idx] = off; g_cursor[idx] = off; }
    if (b == SCAN_NBLK - 1 && t == 0) g_off[NN] = EE;
}

// ---------------- scatter edges into CSR order ----------------
__global__ void scatter_kernel(const int* __restrict__ ei32) {
    __shared__ int s_is64;
    int t = threadIdx.x;
    int is64 = detect_is64(ei32, t, &s_is64);
    int e = blockIdx.x * blockDim.x + t;
    if (e >= EE) return;
    int s, d;
    decode_edge(ei32, is64, e, &s, &d);
    int pos = atomicAdd(&g_cursor[d], 1);
    g_srcSorted[pos] = s;
}

// ---------------- softmax aggregation ----------------
// Warp per dst node; half-warp (16 lanes x float4 = 64 ch) per edge, two
// edges in flight. eps hoisted out of the loop (softmax shift invariance);
// exp via ex2 with log2e folded into t.
__global__ void agg_kernel(int sel, const float* __restrict__ tptr) {
    const float4* __restrict__ xin4 = (const float4*)(sel ? g_x1 : g_xenc);
    int gw = (blockIdx.x * blockDim.x + threadIdx.x) >> 5;
    int lane = threadIdx.x & 31;
    if (gw >= NN) return;
    int half = lane >> 4;      // which edge of the pair
    int li = lane & 15;        // float4 channel group
    float t2 = (*tptr) * 1.44269504f;
    int e0 = g_off[gw], e1 = g_off[gw + 1];

    float S0 = 0.f, S1 = 0.f, S2 = 0.f, S3 = 0.f;
    float A0 = 0.f, A1 = 0.f, A2 = 0.f, A3 = 0.f;

    int e = e0 + half;
    for (; e + 2 < e1; e += 4) {           // 2 pair-steps per iter (4 edges/warp)
        int sA = g_srcSorted[e];
        int sB = g_srcSorted[e + 2];
        float4 vA = xin4[sA * 16 + li];
        float4 vB = xin4[sB * 16 + li];
        float r, ex;
        r = fmaxf(vA.x, 0.f); ex = ex2f(r * t2); S0 += ex; A0 += r * ex;
        r = fmaxf(vA.y, 0.f); ex = ex2f(r * t2); S1 += ex; A1 += r * ex;
        r = fmaxf(vA.z, 0.f); ex = ex2f(r * t2); S2 += ex; A2 += r * ex;
        r = fmaxf(vA.w, 0.f); ex = ex2f(r * t2); S3 += ex; A3 += r * ex;
        r = fmaxf(vB.x, 0.f); ex = ex2f(r * t2); S0 += ex; A0 += r * ex;
        r = fmaxf(vB.y, 0.f); ex = ex2f(r * t2); S1 += ex; A1 += r * ex;
        r = fmaxf(vB.z, 0.f); ex = ex2f(r * t2); S2 += ex; A2 += r * ex;
        r = fmaxf(vB.w, 0.f); ex = ex2f(r * t2); S3 += ex; A3 += r * ex;
    }
    if (e < e1) {
        int sA = g_srcSorted[e];
        float4 vA = xin4[sA * 16 + li];
        float r, ex;
        r = fmaxf(vA.x, 0.f); ex = ex2f(r * t2); S0 += ex; A0 += r * ex;
        r = fmaxf(vA.y, 0.f); ex = ex2f(r * t2); S1 += ex; A1 += r * ex;
        r = fmaxf(vA.z, 0.f); ex = ex2f(r * t2); S2 += ex; A2 += r * ex;
        r = fmaxf(vA.w, 0.f); ex = ex2f(r * t2); S3 += ex; A3 += r * ex;
    }
    // merge the two edge-halves (lanes i and i+16 hold the same channels)
    S0 += __shfl_xor_sync(0xffffffffu, S0, 16);
    S1 += __shfl_xor_sync(0xffffffffu, S1, 16);
    S2 += __shfl_xor_sync(0xffffffffu, S2, 16);
    S3 += __shfl_xor_sync(0xffffffffu, S3, 16);
    A0 += __shfl_xor_sync(0xffffffffu, A0, 16);
    A1 += __shfl_xor_sync(0xffffffffu, A1, 16);
    A2 += __shfl_xor_sync(0xffffffffu, A2, 16);
    A3 += __shfl_xor_sync(0xffffffffu, A3, 16);

    if (half == 0) {
        float4 self = xin4[gw * 16 + li];
        float4 o;
        o.x = A0 / (S0 + 1e-16f) + MSG_EPS + self.x;
        o.y = A1 / (S1 + 1e-16f) + MSG_EPS + self.y;
        o.z = A2 / (S2 + 1e-16f) + MSG_EPS + self.z;
        o.w = A3 / (S3 + 1e-16f) + MSG_EPS + self.w;
        ((float4*)g_tmp)[gw * 16 + li] = o;
    }
}

// ------------- fused MLP via tf32 mma (mlp1 and mlp2+final) -------------
#define XSM 68    // Xs/Os stride (64-wide +4)
#define W1S 136   // W1s stride (128-wide +8)
#define W2S 72    // W2s stride (64-wide +8)
#define HSM 132   // Hs stride (128-wide +4)
__global__ void __launch_bounds__(128) mlp_kernel(
    int final_,
    const float* __restrict__ W1, const float* __restrict__ b1,
    const float* __restrict__ g1, const float* __restrict__ be1,
    const float* __restrict__ W2, const float* __restrict__ b2,
    const float* __restrict__ ln1g, const float* __restrict__ ln1b,
    const float* __restrict__ ng, const float* __restrict__ nb,
    const float* __restrict__ lw, const float* __restrict__ lb,
    float* __restrict__ out) {
    __shared__ float    Xs[32 * XSM];
    __shared__ unsigned W1s[64 * W1S];
    __shared__ unsigned W2s[128 * W2S];
    __shared__ float    Hs[32 * HSM];
    __shared__ float    Os[32 * XSM];
    __shared__ float    b1s[128];
    __shared__ float    b2s[64];

    int tid = threadIdx.x;
    int lane = tid & 31, w = tid >> 5;
    int g = lane >> 2, t = lane & 3;
    int mw = w & 1, nw = w >> 1;

    for (int i = tid; i < 64 * 128; i += 128)
        W1s[(i >> 7) * W1S + (i & 127)] = f2tf(W1[i]);
    for (int i = tid; i < 128 * 64; i += 128)
        W2s[(i >> 6) * W2S + (i & 63)] = f2tf(W2[i]);
    b1s[tid] = b1[tid];
    if (tid < 64) b2s[tid] = b2[tid];

    float4 g1v = *(const float4*)(g1 + 4 * lane);
    float4 be1v = *(const float4*)(be1 + 4 * lane);
    float2 l1g2, l1b2, ngx2, nbx2, ngh2, nbh2, lwx2, lwh2;
    float lbv = 0.f;
    if (final_) {
        l1g2 = *(const float2*)(ln1g + 2 * lane);
        l1b2 = *(const float2*)(ln1b + 2 * lane);
        ngx2 = *(const float2*)(ng + 2 * lane);
        nbx2 = *(const float2*)(nb + 2 * lane);
        ngh2 = *(const float2*)(ng + 64 + 2 * lane);
        nbh2 = *(const float2*)(nb + 64 + 2 * lane);
        lwx2 = *(const float2*)(lw + 2 * lane);
        lwh2 = *(const float2*)(lw + 64 + 2 * lane);
        lbv = lb[0];
    }
    __syncthreads();

    for (int tile = blockIdx.x; tile < NTILES; tile += gridDim.x) {
        int r0 = tile * 32;
        __syncthreads();
        for (int i = tid; i < 32 * 16; i += 128) {
            int r = i >> 4, c4 = i & 15;
            int row = r0 + r;
            float4 v = (row < NN) ? ((const float4*)(g_tmp + (size_t)row * HH))[c4]
                                  : make_float4(0.f, 0.f, 0.f, 0.f);
            float* p = &Xs[r * XSM + 4 * c4];
            p[0] = __uint_as_float(f2tf(v.x));
            p[1] = __uint_as_float(f2tf(v.y));
            p[2] = __uint_as_float(f2tf(v.z));
            p[3] = __uint_as_float(f2tf(v.w));
        }
        __syncthreads();

        // ---- GEMM1 ----
        {
            float acc[8][4];
#pragma unroll
            for (int i = 0; i < 8; i++)
#pragma unroll
                for (int j = 0; j < 4; j++) acc[i][j] = 0.f;
#pragma unroll
            for (int ks = 0; ks < 8; ks++) {
                int k0 = ks * 8;
                unsigned a0 = __float_as_uint(Xs[(mw * 16 + g) * XSM + k0 + t]);
                unsigned a1 = __float_as_uint(Xs[(mw * 16 + g + 8) * XSM + k0 + t]);
                unsigned a2 = __float_as_uint(Xs[(mw * 16 + g) * XSM + k0 + t + 4]);
                unsigned a3 = __float_as_uint(Xs[(mw * 16 + g + 8) * XSM + k0 + t + 4]);
#pragma unroll
                for (int nt = 0; nt < 8; nt++) {
                    int n0 = nw * 64 + nt * 8;
                    unsigned b0 = W1s[(k0 + t) * W1S + n0 + g];
                    unsigned b1f = W1s[(k0 + t + 4) * W1S + n0 + g];
                    mma8(acc[nt][0], acc[nt][1], acc[nt][2], acc[nt][3],
                         a0, a1, a2, a3, b0, b1f);
                }
            }
#pragma unroll
            for (int nt = 0; nt < 8; nt++) {
                int col = nw * 64 + nt * 8 + 2 * t;
                int r = mw * 16 + g;
                *(float2*)&Hs[r * HSM + col] =
                    make_float2(acc[nt][0] + b1s[col], acc[nt][1] + b1s[col + 1]);
                *(float2*)&Hs[(r + 8) * HSM + col] =
                    make_float2(acc[nt][2] + b1s[col], acc[nt][3] + b1s[col + 1]);
            }
        }
        __syncthreads();

        // ---- LN + relu per row ----
        for (int rr = w * 8; rr < w * 8 + 8; rr++) {
            float4 v = *(float4*)&Hs[rr * HSM + 4 * lane];
            float s = (v.x + v.y) + (v.z + v.w);
            float q = (v.x * v.x + v.y * v.y) + (v.z * v.z + v.w * v.w);
#pragma unroll
            for (int o = 16; o; o >>= 1) {
                s += __shfl_xor_sync(0xffffffffu, s, o);
                q += __shfl_xor_sync(0xffffffffu, q, o);
            }
            float mu = s * (1.f / HX);
            float rs = rsqrtf(q * (1.f / HX) - mu * mu + 1e-5f);
            float h0 = fmaxf((v.x - mu) * rs * g1v.x + be1v.x, 0.f);
            float h1 = fmaxf((v.y - mu) * rs * g1v.y + be1v.y, 0.f);
            float h2 = fmaxf((v.z - mu) * rs * g1v.z + be1v.z, 0.f);
            float h3 = fmaxf((v.w - mu) * rs * g1v.w + be1v.w, 0.f);
            float* p = &Hs[rr * HSM + 4 * lane];
            p[0] = __uint_as_float(f2tf(h0));
            p[1] = __uint_as_float(f2tf(h1));
            p[2] = __uint_as_float(f2tf(h2));
            p[3] = __uint_as_float(f2tf(h3));
        }
        __syncthreads();

        // ---- GEMM2 ----
        float acc2[4][4];
#pragma unroll
        for (int i = 0; i < 4; i++)
#pragma unroll
            for (int j = 0; j < 4; j++) acc2[i][j] = 0.f;
#pragma unroll
        for (int ks = 0; ks < 16; ks++) {
            int k0 = ks * 8;
            unsigned a0 = __float_as_uint(Hs[(mw * 16 + g) * HSM + k0 + t]);
            unsigned a1 = __float_as_uint(Hs[(mw * 16 + g + 8) * HSM + k0 + t]);
            unsigned a2 = __float_as_uint(Hs[(mw * 16 + g) * HSM + k0 + t + 4]);
            unsigned a3 = __float_as_uint(Hs[(mw * 16 + g + 8) * HSM + k0 + t + 4]);
#pragma unroll
            for (int nt = 0; nt < 4; nt++) {
                int n0 = nw * 32 + nt * 8;
                unsigned b0 = W2s[(k0 + t) * W2S + n0 + g];
                unsigned b1f = W2s[(k0 + t + 4) * W2S + n0 + g];
                mma8(acc2[nt][0], acc2[nt][1], acc2[nt][2], acc2[nt][3],
                     a0, a1, a2, a3, b0, b1f);
            }
        }

        if (!final_) {
#pragma unroll
            for (int nt = 0; nt < 4; nt++) {
                int col = nw * 32 + nt * 8 + 2 * t;
                int row = r0 + mw * 16 + g;
                if (row < NN) {
                    float2 v = make_float2(acc2[nt][0] + b2s[col], acc2[nt][1] + b2s[col + 1]);
                    *(float2*)&g_x1[(size_t)row * HH + col] = v;
                }
                if (row + 8 < NN) {
                    float2 v = make_float2(acc2[nt][2] + b2s[col], acc2[nt][3] + b2s[col + 1]);
                    *(float2*)&g_x1[(size_t)(row + 8) * HH + col] = v;
                }
            }
        } else {
#pragma unroll
            for (int nt = 0; nt < 4; nt++) {
                int col = nw * 32 + nt * 8 + 2 * t;
                int r = mw * 16 + g;
                *(float2*)&Os[r * XSM + col] =
                    make_float2(acc2[nt][0] + b2s[col], acc2[nt][1] + b2s[col + 1]);
                *(float2*)&Os[(r + 8) * XSM + col] =
                    make_float2(acc2[nt][2] + b2s[col], acc2[nt][3] + b2s[col + 1]);
            }
            __syncthreads();
            for (int rr = w * 8; rr < w * 8 + 8; rr++) {
                int row = r0 + rr;
                if (row >= NN) continue;
                float2 hv = *(float2*)&Os[rr * XSM + 2 * lane];
                float2 xv = *(const float2*)&g_x1[(size_t)row * HH + 2 * lane];

                float s = hv.x + hv.y;
                float q = hv.x * hv.x + hv.y * hv.y;
#pragma unroll
                for (int o = 16; o; o >>= 1) {
                    s += __shfl_xor_sync(0xffffffffu, s, o);
                    q += __shfl_xor_sync(0xffffffffu, q, o);
                }
                float muh = s * (1.f / 64.f);
                float rsh = rsqrtf(q * (1.f / 64.f) - muh * muh + 1e-5f);
                float hn0 = fmaxf((hv.x - muh) * rsh * l1g2.x + l1b2.x, 0.f);
                float hn1 = fmaxf((hv.y - muh) * rsh * l1g2.y + l1b2.y, 0.f);

                float s2 = xv.x + xv.y + hn0 + hn1;
                float q2 = xv.x * xv.x + xv.y * xv.y + hn0 * hn0 + hn1 * hn1;
#pragma unroll
                for (int o = 16; o; o >>= 1) {
                    s2 += __shfl_xor_sync(0xffffffffu, s2, o);
                    q2 += __shfl_xor_sync(0xffffffffu, q2, o);
                }
                float mu2 = s2 * (1.f / 128.f);
                float rs2 = rsqrtf(q2 * (1.f / 128.f) - mu2 * mu2 + 1e-5f);
                float d = fmaxf((xv.x - mu2) * rs2 * ngx2.x + nbx2.x, 0.f) * lwx2.x
                        + fmaxf((xv.y - mu2) * rs2 * ngx2.y + nbx2.y, 0.f) * lwx2.y
                        + fmaxf((hn0 - mu2) * rs2 * ngh2.x + nbh2.x, 0.f) * lwh2.x
                        + fmaxf((hn1 - mu2) * rs2 * ngh2.y + nbh2.y, 0.f) * lwh2.y;
#pragma unroll
                for (int o = 16; o; o >>= 1) d += __shfl_xor_sync(0xffffffffu, d, o);
                if (lane == 0) out[row] = d + lbv;
            }
        }
    }

    if (final_) {
        for (int i = blockIdx.x * blockDim.x + tid; i < NN; i += gridDim.x * blockDim.x)
            g_cnt[i] = 0;
        int i = blockIdx.x * blockDim.x + tid;
        if (i < SCAN_NBLK) *((unsigned long long*)&g_state[i]) = 0ULL;
    }
}

// ---------------- launch ----------------
extern "C" void kernel_launch(void* const* d_in, const int* in_sizes, int n_in,
                              void* d_out, int out_size) {
    const float* x    = (const float*)d_in[0];
    const void*  ei   = d_in[1];
    const float* encW = (const float*)d_in[2];
    const float* encB = (const float*)d_in[3];
    const float* t    = (const float*)d_in[4];
    const float* W1   = (const float*)d_in[5];
    const float* b1   = (const float*)d_in[6];
    const float* g1   = (const float*)d_in[7];
    const float* be1  = (const float*)d_in[8];
    const float* W2   = (const float*)d_in[9];
    const float* b2   = (const float*)d_in[10];
    const float* ln1g = (const float*)d_in[11];
    const float* ln1b = (const float*)d_in[12];
    const float* ng   = (const float*)d_in[13];
    const float* nb   = (const float*)d_in[14];
    const float* lw   = (const float*)d_in[15];
    const float* lb   = (const float*)d_in[16];
    float* out = (float*)d_out;

    const int AGG_BLOCKS = (NN * 32 + 255) / 256;

    enc_count_kernel<<<FUSE_GRID, 128>>>(x, encW, encB, (const int*)ei);
    scan_lb_kernel<<<SCAN_NBLK, 256>>>();
    scatter_kernel<<<(EE + 255) / 256, 256>>>((const int*)ei);
    agg_kernel<<<AGG_BLOCKS, 256>>>(0, t);               // 4th launch -> ncu
    mlp_kernel<<<296, 128>>>(0, W1, b1, g1, be1, W2, b2,
                             ln1g, ln1b, ng, nb, lw, lb, out);
    agg_kernel<<<AGG_BLOCKS, 256>>>(1, t);
    mlp_kernel<<<296, 128>>>(1, W1, b1, g1, be1, W2, b2,
                             ln1g, ln1b, ng, nb, lw, lb, out);
}